// round 13
// baseline (speedup 1.0000x reference)
#include <cuda_runtime.h>
#include <cuda_bf16.h>
#include <cstdint>
#include <math.h>

#define Bb 8
#define Cc 256
#define Hh 48
#define Ww 48
#define Nn 2304
#define NC (Nn*Cc)
#define NR (Bb*Nn)
#define CAP 112
static const long long NNL = (long long)Nn * (long long)Nn;

// ---------------- scratch (static device globals — allocation-guard safe) ----
__device__ float g_X[Bb*NC];                     // (B,N,C) fp32
__device__ float g_S[(long long)Bb*Nn*Nn];       // logits fp32
__device__ __nv_bfloat16 g_Xhi[Bb*NC], g_Xlo[Bb*NC];
__device__ __nv_bfloat16 g_Qhi[Bb*NC], g_Qlo[Bb*NC];
__device__ __nv_bfloat16 g_Khi[Bb*NC], g_Klo[Bb*NC];
__device__ __nv_bfloat16 g_Xdh[Bb*NC], g_Xdl[Bb*NC];
__device__ __nv_bfloat16 g_Nh[Bb*NC],  g_Nl[Bb*NC];
__device__ __nv_bfloat16 g_PhiH[Cc*Cc], g_PhiL[Cc*Cc];
__device__ __nv_bfloat16 g_PsiH[Cc*Cc], g_PsiL[Cc*Cc];
__device__ __nv_bfloat16 g_W0h[Cc*Cc], g_W0l[Cc*Cc];
__device__ __nv_bfloat16 g_W1h[Cc*Cc], g_W1l[Cc*Cc];

// ---------------- PTX helpers (base-target features, sm_80 era) --------------
__device__ __forceinline__ uint32_t smem_u32(const void* p) {
    uint32_t a;
    asm("{ .reg .u64 t; cvta.to.shared.u64 t, %1; cvt.u32.u64 %0, t; }" : "=r"(a) : "l"(p));
    return a;
}
__device__ __forceinline__ void cp16(uint32_t dst, const void* src) {
    asm volatile("cp.async.cg.shared.global [%0], [%1], 16;" :: "r"(dst), "l"(src));
}
#define CP_COMMIT() asm volatile("cp.async.commit_group;" ::: "memory")
#define CP_WAIT(n)  asm volatile("cp.async.wait_group %0;" :: "n"(n) : "memory")

#define LDSM4(r, a) \
    asm volatile("ldmatrix.sync.aligned.m8n8.x4.shared.b16 {%0,%1,%2,%3}, [%4];" \
        : "=r"((r)[0]),"=r"((r)[1]),"=r"((r)[2]),"=r"((r)[3]) : "r"(a))
#define MMA16816(d, a, b) \
    asm volatile("mma.sync.aligned.m16n8k16.row.col.f32.bf16.bf16.f32 " \
        "{%0,%1,%2,%3}, {%4,%5,%6,%7}, {%8,%9}, {%0,%1,%2,%3};" \
        : "+f"((d)[0]),"+f"((d)[1]),"+f"((d)[2]),"+f"((d)[3]) \
        : "r"((a)[0]),"r"((a)[1]),"r"((a)[2]),"r"((a)[3]), "r"((b)[0]),"r"((b)[1]))

__device__ __forceinline__ uint32_t swz(uint32_t x) { return x ^ ((x >> 3) & 0x70); }

__device__ __forceinline__ void store_split2(__nv_bfloat16* hi, __nv_bfloat16* lo,
                                             size_t off, float a, float b) {
    __nv_bfloat16 ah = __float2bfloat16(a), bh = __float2bfloat16(b);
    __nv_bfloat162 h2; h2.x = ah; h2.y = bh;
    *(__nv_bfloat162*)(hi + off) = h2;
    __nv_bfloat162 l2;
    l2.x = __float2bfloat16(a - __bfloat162float(ah));
    l2.y = __float2bfloat16(b - __bfloat162float(bh));
    *(__nv_bfloat162*)(lo + off) = l2;
}

// ---------------------------------------------------------------------------
// 1) Pack: x (B,C,N) -> X (B,N,C) fp32 + bf16 hi/lo
// ---------------------------------------------------------------------------
__global__ void k_pack(const float* __restrict__ x) {
    __shared__ float t[32][33];
    int b = blockIdx.z;
    int n0 = blockIdx.x * 32, c0 = blockIdx.y * 32;
    int tx = threadIdx.x, ty = threadIdx.y;
    const float* xb = x + (size_t)b * Cc * Nn;
    #pragma unroll
    for (int i = 0; i < 4; i++)
        t[ty + 8*i][tx] = xb[(size_t)(c0 + ty + 8*i) * Nn + n0 + tx];
    __syncthreads();
    #pragma unroll
    for (int i = 0; i < 4; i++) {
        float v = t[tx][ty + 8*i];
        size_t o = (size_t)b * NC + (size_t)(n0 + ty + 8*i) * Cc + c0 + tx;
        g_X[o] = v;
        __nv_bfloat16 h = __float2bfloat16(v);
        g_Xhi[o] = h;
        g_Xlo[o] = __float2bfloat16(v - __bfloat162float(h));
    }
}

__global__ void k_splitw(const float* __restrict__ phi, const float* __restrict__ psi,
                         const float* __restrict__ w0,  const float* __restrict__ w1) {
    int i = blockIdx.x * 256 + threadIdx.x;
    float v;
    __nv_bfloat16 h;
    v = phi[i]; h = __float2bfloat16(v); g_PhiH[i] = h; g_PhiL[i] = __float2bfloat16(v - __bfloat162float(h));
    v = psi[i]; h = __float2bfloat16(v); g_PsiH[i] = h; g_PsiL[i] = __float2bfloat16(v - __bfloat162float(h));
    v = w0[i];  h = __float2bfloat16(v); g_W0h[i]  = h; g_W0l[i]  = __float2bfloat16(v - __bfloat162float(h));
    v = w1[i];  h = __float2bfloat16(v); g_W1h[i]  = h; g_W1l[i]  = __float2bfloat16(v - __bfloat162float(h));
}

// ---------------------------------------------------------------------------
// 2) Q/K dual projection, HMMA 3-term. CTA 128(tok) x 64(d), swizzled smem,
//    2-stage single-sync pipeline. Term-major MMA order (dep-chain broken).
// ---------------------------------------------------------------------------
#define QKX_TILE 8192            // 128x32 bf16 swizzled
#define QKW_TILE 4096            // 64x32 bf16 swizzled
#define QK_STAGE_B (2*QKX_TILE + 4*QKW_TILE)  // 32768
#define QK_SMEM (2*QK_STAGE_B)                // 65536

__global__ void __launch_bounds__(256, 2) k_qk_mma() {
    extern __shared__ char smQ[];
    int tid = threadIdx.x, wid = tid >> 5, lane = tid & 31;
    int b = blockIdx.z;
    int arow = blockIdx.y * 128;
    int d0 = blockIdx.x * 64;

    const __nv_bfloat16* srcX[2] = {
        g_Xhi + (size_t)b*NC + (size_t)arow*Cc,
        g_Xlo + (size_t)b*NC + (size_t)arow*Cc
    };
    const __nv_bfloat16* srcW[4] = {
        g_PhiH + (size_t)d0*Cc, g_PhiL + (size_t)d0*Cc,
        g_PsiH + (size_t)d0*Cc, g_PsiL + (size_t)d0*Cc
    };

    int wm = (wid & 3) * 32;
    int wn = (wid >> 2) * 32;

    float accQ[2][4][4], accK[2][4][4];
    #pragma unroll
    for (int mi = 0; mi < 2; mi++)
        #pragma unroll
        for (int ni = 0; ni < 4; ni++)
            #pragma unroll
            for (int r = 0; r < 4; r++) { accQ[mi][ni][r] = 0.f; accK[mi][ni][r] = 0.f; }

    auto load_qk = [&](int st, int k0) {
        char* base = smQ + st * QK_STAGE_B;
        #pragma unroll
        for (int t = 0; t < 2; t++) {
            char* dst = base + t * QKX_TILE;
            #pragma unroll
            for (int i = 0; i < 2; i++) {
                int chunk = i * 256 + tid;
                int r = chunk >> 2, c4 = chunk & 3;
                cp16(smem_u32(dst + swz(r*64 + c4*16)), srcX[t] + (size_t)r*Cc + k0 + c4*8);
            }
        }
        int r = tid >> 2, c4 = tid & 3;
        #pragma unroll
        for (int t = 0; t < 4; t++) {
            char* dst = base + 2*QKX_TILE + t * QKW_TILE;
            cp16(smem_u32(dst + swz(r*64 + c4*16)), srcW[t] + (size_t)r*Cc + k0 + c4*8);
        }
    };

    load_qk(0, 0);
    CP_COMMIT();

    int arl = lane & 15, ach = lane >> 4;
    int b8r = (lane & 7) + ((lane >> 4) << 3);
    int bch = (lane >> 3) & 1;

    for (int ch = 0; ch < 8; ch++) {
        CP_WAIT(0);
        __syncthreads();
        if (ch < 7) {
            load_qk((ch + 1) & 1, (ch + 1) * 32);
            CP_COMMIT();
        }

        char* base = smQ + (ch & 1) * QK_STAGE_B;
        char* tXh  = base;
        char* tXl  = base + QKX_TILE;
        char* tPhH = base + 2*QKX_TILE;
        char* tPhL = base + 2*QKX_TILE + QKW_TILE;
        char* tPsH = base + 2*QKX_TILE + 2*QKW_TILE;
        char* tPsL = base + 2*QKX_TILE + 3*QKW_TILE;

        #pragma unroll
        for (int ks = 0; ks < 2; ks++) {
            uint32_t bph[8], bpl[8], bsh[8], bsl[8];
            LDSM4(bph + 0, smem_u32(tPhH + swz((wn + b8r)*64 + ks*32 + bch*16)));
            LDSM4(bph + 4, smem_u32(tPhH + swz((wn + 16 + b8r)*64 + ks*32 + bch*16)));
            LDSM4(bpl + 0, smem_u32(tPhL + swz((wn + b8r)*64 + ks*32 + bch*16)));
            LDSM4(bpl + 4, smem_u32(tPhL + swz((wn + 16 + b8r)*64 + ks*32 + bch*16)));
            LDSM4(bsh + 0, smem_u32(tPsH + swz((wn + b8r)*64 + ks*32 + bch*16)));
            LDSM4(bsh + 4, smem_u32(tPsH + swz((wn + 16 + b8r)*64 + ks*32 + bch*16)));
            LDSM4(bsl + 0, smem_u32(tPsL + swz((wn + b8r)*64 + ks*32 + bch*16)));
            LDSM4(bsl + 4, smem_u32(tPsL + swz((wn + 16 + b8r)*64 + ks*32 + bch*16)));
            #pragma unroll
            for (int mi = 0; mi < 2; mi++) {
                uint32_t xh[4], xl[4];
                LDSM4(xh, smem_u32(tXh + swz((wm + mi*16 + arl)*64 + ks*32 + ach*16)));
                LDSM4(xl, smem_u32(tXl + swz((wm + mi*16 + arl)*64 + ks*32 + ach*16)));
                // term-major: 8 independent MMAs between reuses of each acc
                #pragma unroll
                for (int ni = 0; ni < 4; ni++) MMA16816(accQ[mi][ni], xh, bph + ni*2);
                #pragma unroll
                for (int ni = 0; ni < 4; ni++) MMA16816(accK[mi][ni], xh, bsh + ni*2);
                #pragma unroll
                for (int ni = 0; ni < 4; ni++) MMA16816(accQ[mi][ni], xh, bpl + ni*2);
                #pragma unroll
                for (int ni = 0; ni < 4; ni++) MMA16816(accK[mi][ni], xh, bsl + ni*2);
                #pragma unroll
                for (int ni = 0; ni < 4; ni++) MMA16816(accQ[mi][ni], xl, bph + ni*2);
                #pragma unroll
                for (int ni = 0; ni < 4; ni++) MMA16816(accK[mi][ni], xl, bsh + ni*2);
            }
        }
    }

    #pragma unroll
    for (int mi = 0; mi < 2; mi++)
        #pragma unroll
        for (int ni = 0; ni < 4; ni++) {
            int r0 = arow + wm + mi*16 + (lane >> 2);
            int c0v = d0 + wn + ni*8 + (lane & 3)*2;
            size_t o0 = (size_t)b*NC + (size_t)r0*Cc + c0v;
            size_t o1 = o0 + (size_t)8*Cc;
            store_split2(g_Qhi, g_Qlo, o0, accQ[mi][ni][0], accQ[mi][ni][1]);
            store_split2(g_Qhi, g_Qlo, o1, accQ[mi][ni][2], accQ[mi][ni][3]);
            store_split2(g_Khi, g_Klo, o0, accK[mi][ni][0], accK[mi][ni][1]);
            store_split2(g_Khi, g_Klo, o1, accK[mi][ni][2], accK[mi][ni][3]);
        }
}

// ---------------------------------------------------------------------------
// 3) Logits: L = Q @ K^T. CTA 128x128, 128 threads, warp tile 64x64,
//    3-stage pipeline, 2 CTAs/SM. Term-major MMA order (32 independent MMAs
//    between reuses of any accumulator).
// ---------------------------------------------------------------------------
#define LTILE_B 8192             // 128x32 bf16 swizzled
#define LSTAGE_B (4*LTILE_B)     // 32768
#define SM_LOGITS_BYTES (3*LSTAGE_B)   // 98304

__device__ __forceinline__ void l_load_stage(char* smbase, int st,
        const __nv_bfloat16* Ah, const __nv_bfloat16* Al,
        const __nv_bfloat16* Bh, const __nv_bfloat16* Bl,
        int k0, int tid) {
    const __nv_bfloat16* srcs[4] = {Ah, Al, Bh, Bl};
    char* stb = smbase + st * LSTAGE_B;
    #pragma unroll
    for (int t = 0; t < 4; t++) {
        char* dst = stb + t * LTILE_B;
        #pragma unroll
        for (int i = 0; i < 4; i++) {
            int chunk = i * 128 + tid;
            int r = chunk >> 2, c4 = chunk & 3;
            cp16(smem_u32(dst + swz(r*64 + c4*16)), srcs[t] + (size_t)r*Cc + k0 + c4*8);
        }
    }
}

__global__ void __launch_bounds__(128, 2) k_logits_mma() {
    extern __shared__ char smL[];
    int tid = threadIdx.x, wid = tid >> 5, lane = tid & 31;
    int b = blockIdx.z;
    int arow = blockIdx.y * 128;
    int brow = blockIdx.x * 128;

    const __nv_bfloat16* Ah = g_Qhi + (size_t)b*NC + (size_t)arow*Cc;
    const __nv_bfloat16* Al = g_Qlo + (size_t)b*NC + (size_t)arow*Cc;
    const __nv_bfloat16* Bh = g_Khi + (size_t)b*NC + (size_t)brow*Cc;
    const __nv_bfloat16* Bl = g_Klo + (size_t)b*NC + (size_t)brow*Cc;

    int wm = (wid & 1) * 64;
    int wn = (wid >> 1) * 64;

    float acc[4][8][4];
    #pragma unroll
    for (int mi = 0; mi < 4; mi++)
        #pragma unroll
        for (int nj = 0; nj < 8; nj++)
            #pragma unroll
            for (int r = 0; r < 4; r++) acc[mi][nj][r] = 0.f;

    l_load_stage(smL, 0, Ah, Al, Bh, Bl, 0, tid);
    CP_COMMIT();
    l_load_stage(smL, 1, Ah, Al, Bh, Bl, 32, tid);
    CP_COMMIT();

    int arl = lane & 15, ach = lane >> 4;
    int b8r = (lane & 7) + ((lane >> 4) << 3);
    int bch = (lane >> 3) & 1;

    for (int ch = 0; ch < 8; ch++) {
        if (ch < 7) { CP_WAIT(1); } else { CP_WAIT(0); }
        __syncthreads();
        if (ch + 2 < 8) {
            l_load_stage(smL, (ch + 2) % 3, Ah, Al, Bh, Bl, (ch + 2) * 32, tid);
            CP_COMMIT();
        }

        char* stb = smL + (ch % 3) * LSTAGE_B;
        char* tAh = stb;
        char* tAl = stb + LTILE_B;
        char* tBh = stb + 2*LTILE_B;
        char* tBl = stb + 3*LTILE_B;

        #pragma unroll
        for (int ks = 0; ks < 2; ks++) {
            uint32_t ah[4][4], al[4][4], bh[16], bl[16];
            #pragma unroll
            for (int mi = 0; mi < 4; mi++) {
                LDSM4(ah[mi], smem_u32(tAh + swz((wm + mi*16 + arl)*64 + ks*32 + ach*16)));
                LDSM4(al[mi], smem_u32(tAl + swz((wm + mi*16 + arl)*64 + ks*32 + ach*16)));
            }
            #pragma unroll
            for (int t = 0; t < 4; t++) {
                LDSM4(bh + t*4, smem_u32(tBh + swz((wn + t*16 + b8r)*64 + ks*32 + bch*16)));
                LDSM4(bl + t*4, smem_u32(tBl + swz((wn + t*16 + b8r)*64 + ks*32 + bch*16)));
            }
            // term-major: every acc reused only after 32 independent MMAs
            #pragma unroll
            for (int mi = 0; mi < 4; mi++)
                #pragma unroll
                for (int nj = 0; nj < 8; nj++) MMA16816(acc[mi][nj], ah[mi], bh + nj*2);
            #pragma unroll
            for (int mi = 0; mi < 4; mi++)
                #pragma unroll
                for (int nj = 0; nj < 8; nj++) MMA16816(acc[mi][nj], ah[mi], bl + nj*2);
            #pragma unroll
            for (int mi = 0; mi < 4; mi++)
                #pragma unroll
                for (int nj = 0; nj < 8; nj++) MMA16816(acc[mi][nj], al[mi], bh + nj*2);
        }
    }

    float* Cp = g_S + (size_t)b * NNL;
    int r0 = arow + wm + (lane >> 2);
    int c0 = brow + wn + (lane & 3) * 2;
    #pragma unroll
    for (int mi = 0; mi < 4; mi++)
        #pragma unroll
        for (int nj = 0; nj < 8; nj++) {
            float* p0 = Cp + (size_t)(r0 + mi*16) * Nn + c0 + nj*8;
            p0[0] = acc[mi][nj][0]; p0[1] = acc[mi][nj][1];
            float* p1 = p0 + (size_t)8 * Nn;
            p1[0] = acc[mi][nj][2]; p1[1] = acc[mi][nj][3];
        }
}

// ---------------------------------------------------------------------------
// 4) Fused softmax + threshold + compaction + sparse gather (one block/row).
// ---------------------------------------------------------------------------
__global__ void __launch_bounds__(288) k_smx_nbr() {
    __shared__ float ex[Nn];
    __shared__ float wred[9];
    __shared__ int wcnt[9], wbase[9];
    __shared__ int s_idx[CAP];
    __shared__ float s_val[CAP];
    __shared__ float s_diag;
    __shared__ int s_cnt;

    int b = blockIdx.y, n = blockIdx.x, tid = threadIdx.x;
    int wid = tid >> 5, lane = tid & 31;
    const float* row = g_S + (long long)b * NNL + (long long)n * Nn;

    float4 v0 = ((const float4*)row)[tid];
    float4 v1 = ((const float4*)row)[tid + 288];
    float mx = fmaxf(fmaxf(v0.x, v0.y), fmaxf(v0.z, v0.w));
    mx = fmaxf(mx, fmaxf(fmaxf(v1.x, v1.y), fmaxf(v1.z, v1.w)));
    #pragma unroll
    for (int o = 16; o; o >>= 1) mx = fmaxf(mx, __shfl_xor_sync(0xffffffffu, mx, o));
    if (!lane) wred[wid] = mx;
    __syncthreads();
    mx = wred[0];
    #pragma unroll
    for (int w = 1; w < 9; w++) mx = fmaxf(mx, wred[w]);
    __syncthreads();

    float4 e0, e1;
    e0.x = __expf(v0.x - mx); e0.y = __expf(v0.y - mx);
    e0.z = __expf(v0.z - mx); e0.w = __expf(v0.w - mx);
    e1.x = __expf(v1.x - mx); e1.y = __expf(v1.y - mx);
    e1.z = __expf(v1.z - mx); e1.w = __expf(v1.w - mx);
    ((float4*)ex)[tid] = e0;
    ((float4*)ex)[tid + 288] = e1;
    float s = e0.x + e0.y + e0.z + e0.w + e1.x + e1.y + e1.z + e1.w;
    #pragma unroll
    for (int o = 16; o; o >>= 1) s += __shfl_xor_sync(0xffffffffu, s, o);
    if (!lane) wred[wid] = s;
    __syncthreads();
    s = 0.f;
    #pragma unroll
    for (int w = 0; w < 9; w++) s += wred[w];
    float inv = 1.f / s;

    unsigned msks[8];
    int cnt = 0;
    int base_m = wid * 256;
    #pragma unroll
    for (int it = 0; it < 8; it++) {
        int m = base_m + it*32 + lane;
        float p = ex[m] * inv;
        bool ge = (p >= 0.01f);
        if (m == n) s_diag = ge ? p : 0.f;
        bool keep = ge && (m != n);
        unsigned k = __ballot_sync(0xffffffffu, keep);
        msks[it] = k;
        cnt += __popc(k);
    }
    if (!lane) wcnt[wid] = cnt;
    __syncthreads();
    if (tid == 0) {
        int t = 0;
        #pragma unroll
        for (int w = 0; w < 9; w++) { wbase[w] = t; t += wcnt[w]; }
        s_cnt = t;
    }
    __syncthreads();

    int bp = wbase[wid];
    #pragma unroll
    for (int it = 0; it < 8; it++) {
        unsigned k = msks[it];
        if ((k >> lane) & 1) {
            int m = base_m + it*32 + lane;
            int pos = bp + __popc(k & ((1u << lane) - 1));
            s_idx[pos] = m;
            s_val[pos] = ex[m] * inv;
        }
        bp += __popc(k);
    }
    __syncthreads();

    if (tid < Cc) {
        int c = tid;
        int y = n / Ww, x = n % Ww;
        const float* Xb = g_X + (size_t)b * NC;

        float acc = 0.f;
        if (y > 0)      acc += Xb[(size_t)(n - Ww) * Cc + c];
        if (y < Hh - 1) acc += Xb[(size_t)(n + Ww) * Cc + c];
        if (x > 0)      acc += Xb[(size_t)(n - 1) * Cc + c];
        if (x < Ww - 1) acc += Xb[(size_t)(n + 1) * Cc + c];

        int cnt2 = s_cnt;
        for (int i = 0; i < cnt2; i++)
            acc += s_val[i] * Xb[(size_t)s_idx[i] * Cc + c];

        size_t o = (size_t)b * NC + (size_t)n * Cc + c;
        __nv_bfloat16 nh = __float2bfloat16(acc);
        g_Nh[o] = nh;
        g_Nl[o] = __float2bfloat16(acc - __bfloat162float(nh));

        float xd = Xb[(size_t)n * Cc + c] * (1.f + s_diag);
        __nv_bfloat16 xh = __float2bfloat16(xd);
        g_Xdh[o] = xh;
        g_Xdl[o] = __float2bfloat16(xd - __bfloat162float(xh));
    }
}

// ---------------------------------------------------------------------------
// 5) Final: out = relu(w0@Xd^T + w1@nbr^T) via HMMA 6-term.
//    CTA 128(d) x 64(n), swizzled smem, 2 CTAs/SM. Term-major within mi.
// ---------------------------------------------------------------------------
#define FW_TILE 8192
#define FX_TILE 4096
#define FIN_STAGE_B (4*FW_TILE + 4*FX_TILE)
#define FIN_SMEM (2*FIN_STAGE_B)

__global__ void __launch_bounds__(256, 2) k_final_mma(float* __restrict__ out) {
    extern __shared__ char smF[];
    int tid = threadIdx.x, wid = tid >> 5, lane = tid & 31;
    int b = blockIdx.z;
    int d0 = blockIdx.y * 128;
    int n0 = blockIdx.x * 64;

    const __nv_bfloat16* srcW[4] = {
        g_W0h + (size_t)d0*Cc, g_W0l + (size_t)d0*Cc,
        g_W1h + (size_t)d0*Cc, g_W1l + (size_t)d0*Cc
    };
    const __nv_bfloat16* srcX[4] = {
        g_Xdh + (size_t)b*NC + (size_t)n0*Cc, g_Xdl + (size_t)b*NC + (size_t)n0*Cc,
        g_Nh  + (size_t)b*NC + (size_t)n0*Cc, g_Nl  + (size_t)b*NC + (size_t)n0*Cc
    };

    int wd = (wid & 1) * 64;
    int wn2 = (wid >> 1) * 16;

    float acc[4][2][4];
    #pragma unroll
    for (int mi = 0; mi < 4; mi++)
        #pragma unroll
        for (int ni = 0; ni < 2; ni++)
            #pragma unroll
            for (int r = 0; r < 4; r++) acc[mi][ni][r] = 0.f;

    auto load_fin = [&](int st, int k0) {
        char* base = smF + st * FIN_STAGE_B;
        #pragma unroll
        for (int t = 0; t < 4; t++) {
            char* dst = base + t * FW_TILE;
            #pragma unroll
            for (int i = 0; i < 2; i++) {
                int chunk = i * 256 + tid;
                int r = chunk >> 2, c4 = chunk & 3;
                cp16(smem_u32(dst + swz(r*64 + c4*16)), srcW[t] + (size_t)r*Cc + k0 + c4*8);
            }
        }
        int r = tid >> 2, c4 = tid & 3;
        #pragma unroll
        for (int t = 0; t < 4; t++) {
            char* dst = base + 4*FW_TILE + t * FX_TILE;
            cp16(smem_u32(dst + swz(r*64 + c4*16)), srcX[t] + (size_t)r*Cc + k0 + c4*8);
        }
    };

    load_fin(0, 0);
    CP_COMMIT();

    int arl = lane & 15, ach = lane >> 4;
    int b8r = (lane & 7) + ((lane >> 4) << 3);
    int bch = (lane >> 3) & 1;

    for (int ch = 0; ch < 8; ch++) {
        CP_WAIT(0);
        __syncthreads();
        if (ch < 7) {
            load_fin((ch + 1) & 1, (ch + 1) * 32);
            CP_COMMIT();
        }

        char* base = smF + (ch & 1) * FIN_STAGE_B;
        char* tW0h = base;
        char* tW0l = base + FW_TILE;
        char* tW1h = base + 2*FW_TILE;
        char* tW1l = base + 3*FW_TILE;
        char* tXh  = base + 4*FW_TILE;
        char* tXl  = base + 4*FW_TILE + FX_TILE;
        char* tNh  = base + 4*FW_TILE + 2*FX_TILE;
        char* tNl  = base + 4*FW_TILE + 3*FX_TILE;

        #pragma unroll
        for (int ks = 0; ks < 2; ks++) {
            uint32_t bxh[4], bxl[4], bnh[4], bnl[4];
            LDSM4(bxh, smem_u32(tXh + swz((wn2 + b8r)*64 + ks*32 + bch*16)));
            LDSM4(bxl, smem_u32(tXl + swz((wn2 + b8r)*64 + ks*32 + bch*16)));
            LDSM4(bnh, smem_u32(tNh + swz((wn2 + b8r)*64 + ks*32 + bch*16)));
            LDSM4(bnl, smem_u32(tNl + swz((wn2 + b8r)*64 + ks*32 + bch*16)));
            // process mi in pairs: 2 mi x 2 ni = 4 independent MMAs per term wave
            #pragma unroll
            for (int mp = 0; mp < 2; mp++) {
                uint32_t w0h[2][4], w0l[2][4], w1h[2][4], w1l[2][4];
                #pragma unroll
                for (int q = 0; q < 2; q++) {
                    int mi = mp*2 + q;
                    LDSM4(w0h[q], smem_u32(tW0h + swz((wd + mi*16 + arl)*64 + ks*32 + ach*16)));
                    LDSM4(w0l[q], smem_u32(tW0l + swz((wd + mi*16 + arl)*64 + ks*32 + ach*16)));
                    LDSM4(w1h[q], smem_u32(tW1h + swz((wd + mi*16 + arl)*64 + ks*32 + ach*16)));
                    LDSM4(w1l[q], smem_u32(tW1l + swz((wd + mi*16 + arl)*64 + ks*32 + ach*16)));
                }
                // term-major across the 2x2 acc group
                #pragma unroll
                for (int q = 0; q < 2; q++)
                    #pragma unroll
                    for (int ni = 0; ni < 2; ni++) MMA16816(acc[mp*2+q][ni], w0h[q], bxh + ni*2);
                #pragma unroll
                for (int q = 0; q < 2; q++)
                    #pragma unroll
                    for (int ni = 0; ni < 2; ni++) MMA16816(acc[mp*2+q][ni], w0h[q], bxl + ni*2);
                #pragma unroll
                for (int q = 0; q < 2; q++)
                    #pragma unroll
                    for (int ni = 0; ni < 2; ni++) MMA16816(acc[mp*2+q][ni], w0l[q], bxh + ni*2);
                #pragma unroll
                for (int q = 0; q < 2; q++)
                    #pragma unroll
                    for (int ni = 0; ni < 2; ni++) MMA16816(acc[mp*2+q][ni], w1h[q], bnh + ni*2);
                #pragma unroll
                for (int q = 0; q < 2; q++)
                    #pragma unroll
                    for (int ni = 0; ni < 2; ni++) MMA16816(acc[mp*2+q][ni], w1h[q], bnl + ni*2);
                #pragma unroll
                for (int q = 0; q < 2; q++)
                    #pragma unroll
                    for (int ni = 0; ni < 2; ni++) MMA16816(acc[mp*2+q][ni], w1l[q], bnh + ni*2);
            }
        }
    }

    #pragma unroll
    for (int mi = 0; mi < 4; mi++)
        #pragma unroll
        for (int ni = 0; ni < 2; ni++) {
            int d = d0 + wd + mi*16 + (lane >> 2);
            int col = n0 + wn2 + ni*8 + (lane & 3)*2;
            float* p0 = out + ((size_t)b * Cc + d) * Nn + col;
            float2 v0;
            v0.x = fmaxf(acc[mi][ni][0], 0.f);
            v0.y = fmaxf(acc[mi][ni][1], 0.f);
            *(float2*)p0 = v0;
            float2 v1;
            v1.x = fmaxf(acc[mi][ni][2], 0.f);
            v1.y = fmaxf(acc[mi][ni][3], 0.f);
            *(float2*)(p0 + (size_t)8 * Nn) = v1;
        }
}

// ---------------------------------------------------------------------------
extern "C" void kernel_launch(void* const* d_in, const int* in_sizes, int n_in,
                              void* d_out, int out_size) {
    const float* x    = (const float*)d_in[0];
    const float* phi  = (const float*)d_in[1];
    const float* psi  = (const float*)d_in[2];
    const float* w0   = (const float*)d_in[3];
    const float* w1   = (const float*)d_in[4];
    float* out = (float*)d_out;

    cudaFuncSetAttribute(k_qk_mma,     cudaFuncAttributeMaxDynamicSharedMemorySize, QK_SMEM);
    cudaFuncSetAttribute(k_logits_mma, cudaFuncAttributeMaxDynamicSharedMemorySize, SM_LOGITS_BYTES);
    cudaFuncSetAttribute(k_final_mma,  cudaFuncAttributeMaxDynamicSharedMemorySize, FIN_SMEM);

    k_pack<<<dim3(Nn/32, Cc/32, Bb), dim3(32, 8)>>>(x);
    k_splitw<<<(Cc*Cc)/256, 256>>>(phi, psi, w0, w1);
    k_qk_mma<<<dim3(Cc/64, Nn/128, Bb), 256, QK_SMEM>>>();
    k_logits_mma<<<dim3(Nn/128, Nn/128, Bb), 128, SM_LOGITS_BYTES>>>();
    k_smx_nbr<<<dim3(Nn, Bb), 288>>>();
    k_final_mma<<<dim3(Nn/64, Cc/128, Bb), 256, FIN_SMEM>>>(out);
}

// round 14
// speedup vs baseline: 1.0044x; 1.0044x over previous
#include <cuda_runtime.h>
#include <cuda_bf16.h>
#include <cstdint>
#include <math.h>

#define Bb 8
#define Cc 256
#define Hh 48
#define Ww 48
#define Nn 2304
#define NC (Nn*Cc)
#define NR (Bb*Nn)
#define CAP 112
static const long long NNL = (long long)Nn * (long long)Nn;

// ---------------- scratch (static device globals — allocation-guard safe) ----
__device__ float g_X[Bb*NC];                     // (B,N,C) fp32
__device__ float g_S[(long long)Bb*Nn*Nn];       // logits fp32
__device__ __nv_bfloat16 g_Xhi[Bb*NC], g_Xlo[Bb*NC];
__device__ __nv_bfloat16 g_Qhi[Bb*NC], g_Qlo[Bb*NC];
__device__ __nv_bfloat16 g_Khi[Bb*NC], g_Klo[Bb*NC];
__device__ __nv_bfloat16 g_Xdh[Bb*NC], g_Xdl[Bb*NC];
__device__ __nv_bfloat16 g_Nh[Bb*NC],  g_Nl[Bb*NC];
__device__ __nv_bfloat16 g_PhiH[Cc*Cc], g_PhiL[Cc*Cc];
__device__ __nv_bfloat16 g_PsiH[Cc*Cc], g_PsiL[Cc*Cc];
__device__ __nv_bfloat16 g_W0h[Cc*Cc], g_W0l[Cc*Cc];
__device__ __nv_bfloat16 g_W1h[Cc*Cc], g_W1l[Cc*Cc];

// ---------------- PTX helpers (base-target features, sm_80 era) --------------
__device__ __forceinline__ uint32_t smem_u32(const void* p) {
    uint32_t a;
    asm("{ .reg .u64 t; cvta.to.shared.u64 t, %1; cvt.u32.u64 %0, t; }" : "=r"(a) : "l"(p));
    return a;
}
__device__ __forceinline__ void cp16(uint32_t dst, const void* src) {
    asm volatile("cp.async.cg.shared.global [%0], [%1], 16;" :: "r"(dst), "l"(src));
}
#define CP_COMMIT() asm volatile("cp.async.commit_group;" ::: "memory")
#define CP_WAIT(n)  asm volatile("cp.async.wait_group %0;" :: "n"(n) : "memory")

#define LDSM4(r, a) \
    asm volatile("ldmatrix.sync.aligned.m8n8.x4.shared.b16 {%0,%1,%2,%3}, [%4];" \
        : "=r"((r)[0]),"=r"((r)[1]),"=r"((r)[2]),"=r"((r)[3]) : "r"(a))
#define MMA16816(d, a, b) \
    asm volatile("mma.sync.aligned.m16n8k16.row.col.f32.bf16.bf16.f32 " \
        "{%0,%1,%2,%3}, {%4,%5,%6,%7}, {%8,%9}, {%0,%1,%2,%3};" \
        : "+f"((d)[0]),"+f"((d)[1]),"+f"((d)[2]),"+f"((d)[3]) \
        : "r"((a)[0]),"r"((a)[1]),"r"((a)[2]),"r"((a)[3]), "r"((b)[0]),"r"((b)[1]))

__device__ __forceinline__ uint32_t swz(uint32_t x) { return x ^ ((x >> 3) & 0x70); }

__device__ __forceinline__ void store_split2(__nv_bfloat16* hi, __nv_bfloat16* lo,
                                             size_t off, float a, float b) {
    __nv_bfloat16 ah = __float2bfloat16(a), bh = __float2bfloat16(b);
    __nv_bfloat162 h2; h2.x = ah; h2.y = bh;
    *(__nv_bfloat162*)(hi + off) = h2;
    __nv_bfloat162 l2;
    l2.x = __float2bfloat16(a - __bfloat162float(ah));
    l2.y = __float2bfloat16(b - __bfloat162float(bh));
    *(__nv_bfloat162*)(lo + off) = l2;
}

// ---------------------------------------------------------------------------
// 1) Pack: x (B,C,N) -> X (B,N,C) fp32 + bf16 hi/lo
// ---------------------------------------------------------------------------
__global__ void k_pack(const float* __restrict__ x) {
    __shared__ float t[32][33];
    int b = blockIdx.z;
    int n0 = blockIdx.x * 32, c0 = blockIdx.y * 32;
    int tx = threadIdx.x, ty = threadIdx.y;
    const float* xb = x + (size_t)b * Cc * Nn;
    #pragma unroll
    for (int i = 0; i < 4; i++)
        t[ty + 8*i][tx] = xb[(size_t)(c0 + ty + 8*i) * Nn + n0 + tx];
    __syncthreads();
    #pragma unroll
    for (int i = 0; i < 4; i++) {
        float v = t[tx][ty + 8*i];
        size_t o = (size_t)b * NC + (size_t)(n0 + ty + 8*i) * Cc + c0 + tx;
        g_X[o] = v;
        __nv_bfloat16 h = __float2bfloat16(v);
        g_Xhi[o] = h;
        g_Xlo[o] = __float2bfloat16(v - __bfloat162float(h));
    }
}

__global__ void k_splitw(const float* __restrict__ phi, const float* __restrict__ psi,
                         const float* __restrict__ w0,  const float* __restrict__ w1) {
    int i = blockIdx.x * 256 + threadIdx.x;
    float v;
    __nv_bfloat16 h;
    v = phi[i]; h = __float2bfloat16(v); g_PhiH[i] = h; g_PhiL[i] = __float2bfloat16(v - __bfloat162float(h));
    v = psi[i]; h = __float2bfloat16(v); g_PsiH[i] = h; g_PsiL[i] = __float2bfloat16(v - __bfloat162float(h));
    v = w0[i];  h = __float2bfloat16(v); g_W0h[i]  = h; g_W0l[i]  = __float2bfloat16(v - __bfloat162float(h));
    v = w1[i];  h = __float2bfloat16(v); g_W1h[i]  = h; g_W1l[i]  = __float2bfloat16(v - __bfloat162float(h));
}

// ---------------------------------------------------------------------------
// 2) Q/K dual projection. CTA 128(tok) x 64(d), 128 THREADS (2x2 warps),
//    warp tile 64tok x 32d per output (accQ+accK = 128 regs, LDSM/MMA = 1/6),
//    3-stage pipeline, 2 CTAs/SM.
// ---------------------------------------------------------------------------
#define QKX_TILE 8192            // 128x32 bf16 swizzled
#define QKW_TILE 4096            // 64x32 bf16 swizzled
#define QK_STAGE_B (2*QKX_TILE + 4*QKW_TILE)  // 32768
#define QK_SMEM (3*QK_STAGE_B)                // 98304

__device__ __forceinline__ void qk_load_stage(char* smbase, int st,
        const __nv_bfloat16* Xh, const __nv_bfloat16* Xl,
        const __nv_bfloat16* PhH, const __nv_bfloat16* PhL,
        const __nv_bfloat16* PsH, const __nv_bfloat16* PsL,
        int k0, int tid) {
    char* base = smbase + st * QK_STAGE_B;
    const __nv_bfloat16* sa[2] = {Xh, Xl};
    #pragma unroll
    for (int t = 0; t < 2; t++) {
        char* dst = base + t * QKX_TILE;
        #pragma unroll
        for (int i = 0; i < 4; i++) {
            int chunk = i * 128 + tid;
            int r = chunk >> 2, c4 = chunk & 3;
            cp16(smem_u32(dst + swz(r*64 + c4*16)), sa[t] + (size_t)r*Cc + k0 + c4*8);
        }
    }
    const __nv_bfloat16* sb[4] = {PhH, PhL, PsH, PsL};
    #pragma unroll
    for (int t = 0; t < 4; t++) {
        char* dst = base + 2*QKX_TILE + t * QKW_TILE;
        #pragma unroll
        for (int i = 0; i < 2; i++) {
            int chunk = i * 128 + tid;
            int r = chunk >> 2, c4 = chunk & 3;
            cp16(smem_u32(dst + swz(r*64 + c4*16)), sb[t] + (size_t)r*Cc + k0 + c4*8);
        }
    }
}

__global__ void __launch_bounds__(128, 2) k_qk_mma() {
    extern __shared__ char smQ[];
    int tid = threadIdx.x, wid = tid >> 5, lane = tid & 31;
    int b = blockIdx.z;
    int arow = blockIdx.y * 128;
    int d0 = blockIdx.x * 64;

    const __nv_bfloat16* Xh = g_Xhi + (size_t)b*NC + (size_t)arow*Cc;
    const __nv_bfloat16* Xl = g_Xlo + (size_t)b*NC + (size_t)arow*Cc;
    const __nv_bfloat16* PhH = g_PhiH + (size_t)d0*Cc;
    const __nv_bfloat16* PhL = g_PhiL + (size_t)d0*Cc;
    const __nv_bfloat16* PsH = g_PsiH + (size_t)d0*Cc;
    const __nv_bfloat16* PsL = g_PsiL + (size_t)d0*Cc;

    int wm = (wid & 1) * 64;     // token offset (2 warps over 128)
    int wd = (wid >> 1) * 32;    // d offset (2 warps over 64)

    float accQ[4][4][4], accK[4][4][4];
    #pragma unroll
    for (int mi = 0; mi < 4; mi++)
        #pragma unroll
        for (int nj = 0; nj < 4; nj++)
            #pragma unroll
            for (int r = 0; r < 4; r++) { accQ[mi][nj][r] = 0.f; accK[mi][nj][r] = 0.f; }

    qk_load_stage(smQ, 0, Xh, Xl, PhH, PhL, PsH, PsL, 0, tid);
    CP_COMMIT();
    qk_load_stage(smQ, 1, Xh, Xl, PhH, PhL, PsH, PsL, 32, tid);
    CP_COMMIT();

    int arl = lane & 15, ach = lane >> 4;
    int b8r = (lane & 7) + ((lane >> 4) << 3);
    int bch = (lane >> 3) & 1;

    for (int ch = 0; ch < 8; ch++) {
        if (ch < 7) { CP_WAIT(1); } else { CP_WAIT(0); }
        __syncthreads();
        if (ch + 2 < 8) {
            qk_load_stage(smQ, (ch + 2) % 3, Xh, Xl, PhH, PhL, PsH, PsL, (ch + 2) * 32, tid);
            CP_COMMIT();
        }

        char* base = smQ + (ch % 3) * QK_STAGE_B;
        char* tXh  = base;
        char* tXl  = base + QKX_TILE;
        char* tPhH = base + 2*QKX_TILE;
        char* tPhL = base + 2*QKX_TILE + QKW_TILE;
        char* tPsH = base + 2*QKX_TILE + 2*QKW_TILE;
        char* tPsL = base + 2*QKX_TILE + 3*QKW_TILE;

        #pragma unroll
        for (int ks = 0; ks < 2; ks++) {
            uint32_t xh[4][4], xl[4][4];
            #pragma unroll
            for (int mi = 0; mi < 4; mi++) {
                LDSM4(xh[mi], smem_u32(tXh + swz((wm + mi*16 + arl)*64 + ks*32 + ach*16)));
                LDSM4(xl[mi], smem_u32(tXl + swz((wm + mi*16 + arl)*64 + ks*32 + ach*16)));
            }
            uint32_t bph[8], bpl[8], bsh[8], bsl[8];
            #pragma unroll
            for (int t = 0; t < 2; t++) {
                LDSM4(bph + t*4, smem_u32(tPhH + swz((wd + t*16 + b8r)*64 + ks*32 + bch*16)));
                LDSM4(bpl + t*4, smem_u32(tPhL + swz((wd + t*16 + b8r)*64 + ks*32 + bch*16)));
                LDSM4(bsh + t*4, smem_u32(tPsH + swz((wd + t*16 + b8r)*64 + ks*32 + bch*16)));
                LDSM4(bsl + t*4, smem_u32(tPsL + swz((wd + t*16 + b8r)*64 + ks*32 + bch*16)));
            }
            // term-major waves; per-acc order: Q: ph,pl,(xl)ph; K: sh,sl,(xl)sh
            #pragma unroll
            for (int mi = 0; mi < 4; mi++)
                #pragma unroll
                for (int nj = 0; nj < 4; nj++) MMA16816(accQ[mi][nj], xh[mi], bph + nj*2);
            #pragma unroll
            for (int mi = 0; mi < 4; mi++)
                #pragma unroll
                for (int nj = 0; nj < 4; nj++) MMA16816(accK[mi][nj], xh[mi], bsh + nj*2);
            #pragma unroll
            for (int mi = 0; mi < 4; mi++)
                #pragma unroll
                for (int nj = 0; nj < 4; nj++) MMA16816(accQ[mi][nj], xh[mi], bpl + nj*2);
            #pragma unroll
            for (int mi = 0; mi < 4; mi++)
                #pragma unroll
                for (int nj = 0; nj < 4; nj++) MMA16816(accK[mi][nj], xh[mi], bsl + nj*2);
            #pragma unroll
            for (int mi = 0; mi < 4; mi++)
                #pragma unroll
                for (int nj = 0; nj < 4; nj++) MMA16816(accQ[mi][nj], xl[mi], bph + nj*2);
            #pragma unroll
            for (int mi = 0; mi < 4; mi++)
                #pragma unroll
                for (int nj = 0; nj < 4; nj++) MMA16816(accK[mi][nj], xl[mi], bsh + nj*2);
        }
    }

    #pragma unroll
    for (int mi = 0; mi < 4; mi++)
        #pragma unroll
        for (int nj = 0; nj < 4; nj++) {
            int r0 = arow + wm + mi*16 + (lane >> 2);
            int c0v = d0 + wd + nj*8 + (lane & 3)*2;
            size_t o0 = (size_t)b*NC + (size_t)r0*Cc + c0v;
            size_t o1 = o0 + (size_t)8*Cc;
            store_split2(g_Qhi, g_Qlo, o0, accQ[mi][nj][0], accQ[mi][nj][1]);
            store_split2(g_Qhi, g_Qlo, o1, accQ[mi][nj][2], accQ[mi][nj][3]);
            store_split2(g_Khi, g_Klo, o0, accK[mi][nj][0], accK[mi][nj][1]);
            store_split2(g_Khi, g_Klo, o1, accK[mi][nj][2], accK[mi][nj][3]);
        }
}

// ---------------------------------------------------------------------------
// 3) Logits: L = Q @ K^T. CTA 128x128, 128 threads, warp tile 64x64,
//    3-stage pipeline, 2 CTAs/SM. (Frozen at R12/R13 config.)
// ---------------------------------------------------------------------------
#define LTILE_B 8192
#define LSTAGE_B (4*LTILE_B)
#define SM_LOGITS_BYTES (3*LSTAGE_B)

__device__ __forceinline__ void l_load_stage(char* smbase, int st,
        const __nv_bfloat16* Ah, const __nv_bfloat16* Al,
        const __nv_bfloat16* Bh, const __nv_bfloat16* Bl,
        int k0, int tid) {
    const __nv_bfloat16* srcs[4] = {Ah, Al, Bh, Bl};
    char* stb = smbase + st * LSTAGE_B;
    #pragma unroll
    for (int t = 0; t < 4; t++) {
        char* dst = stb + t * LTILE_B;
        #pragma unroll
        for (int i = 0; i < 4; i++) {
            int chunk = i * 128 + tid;
            int r = chunk >> 2, c4 = chunk & 3;
            cp16(smem_u32(dst + swz(r*64 + c4*16)), srcs[t] + (size_t)r*Cc + k0 + c4*8);
        }
    }
}

__global__ void __launch_bounds__(128, 2) k_logits_mma() {
    extern __shared__ char smL[];
    int tid = threadIdx.x, wid = tid >> 5, lane = tid & 31;
    int b = blockIdx.z;
    int arow = blockIdx.y * 128;
    int brow = blockIdx.x * 128;

    const __nv_bfloat16* Ah = g_Qhi + (size_t)b*NC + (size_t)arow*Cc;
    const __nv_bfloat16* Al = g_Qlo + (size_t)b*NC + (size_t)arow*Cc;
    const __nv_bfloat16* Bh = g_Khi + (size_t)b*NC + (size_t)brow*Cc;
    const __nv_bfloat16* Bl = g_Klo + (size_t)b*NC + (size_t)brow*Cc;

    int wm = (wid & 1) * 64;
    int wn = (wid >> 1) * 64;

    float acc[4][8][4];
    #pragma unroll
    for (int mi = 0; mi < 4; mi++)
        #pragma unroll
        for (int nj = 0; nj < 8; nj++)
            #pragma unroll
            for (int r = 0; r < 4; r++) acc[mi][nj][r] = 0.f;

    l_load_stage(smL, 0, Ah, Al, Bh, Bl, 0, tid);
    CP_COMMIT();
    l_load_stage(smL, 1, Ah, Al, Bh, Bl, 32, tid);
    CP_COMMIT();

    int arl = lane & 15, ach = lane >> 4;
    int b8r = (lane & 7) + ((lane >> 4) << 3);
    int bch = (lane >> 3) & 1;

    for (int ch = 0; ch < 8; ch++) {
        if (ch < 7) { CP_WAIT(1); } else { CP_WAIT(0); }
        __syncthreads();
        if (ch + 2 < 8) {
            l_load_stage(smL, (ch + 2) % 3, Ah, Al, Bh, Bl, (ch + 2) * 32, tid);
            CP_COMMIT();
        }

        char* stb = smL + (ch % 3) * LSTAGE_B;
        char* tAh = stb;
        char* tAl = stb + LTILE_B;
        char* tBh = stb + 2*LTILE_B;
        char* tBl = stb + 3*LTILE_B;

        #pragma unroll
        for (int ks = 0; ks < 2; ks++) {
            uint32_t ah[4][4], al[4][4], bh[16], bl[16];
            #pragma unroll
            for (int mi = 0; mi < 4; mi++) {
                LDSM4(ah[mi], smem_u32(tAh + swz((wm + mi*16 + arl)*64 + ks*32 + ach*16)));
                LDSM4(al[mi], smem_u32(tAl + swz((wm + mi*16 + arl)*64 + ks*32 + ach*16)));
            }
            #pragma unroll
            for (int t = 0; t < 4; t++) {
                LDSM4(bh + t*4, smem_u32(tBh + swz((wn + t*16 + b8r)*64 + ks*32 + bch*16)));
                LDSM4(bl + t*4, smem_u32(tBl + swz((wn + t*16 + b8r)*64 + ks*32 + bch*16)));
            }
            #pragma unroll
            for (int mi = 0; mi < 4; mi++)
                #pragma unroll
                for (int nj = 0; nj < 8; nj++) MMA16816(acc[mi][nj], ah[mi], bh + nj*2);
            #pragma unroll
            for (int mi = 0; mi < 4; mi++)
                #pragma unroll
                for (int nj = 0; nj < 8; nj++) MMA16816(acc[mi][nj], ah[mi], bl + nj*2);
            #pragma unroll
            for (int mi = 0; mi < 4; mi++)
                #pragma unroll
                for (int nj = 0; nj < 8; nj++) MMA16816(acc[mi][nj], al[mi], bh + nj*2);
        }
    }

    float* Cp = g_S + (size_t)b * NNL;
    int r0 = arow + wm + (lane >> 2);
    int c0 = brow + wn + (lane & 3) * 2;
    #pragma unroll
    for (int mi = 0; mi < 4; mi++)
        #pragma unroll
        for (int nj = 0; nj < 8; nj++) {
            float* p0 = Cp + (size_t)(r0 + mi*16) * Nn + c0 + nj*8;
            p0[0] = acc[mi][nj][0]; p0[1] = acc[mi][nj][1];
            float* p1 = p0 + (size_t)8 * Nn;
            p1[0] = acc[mi][nj][2]; p1[1] = acc[mi][nj][3];
        }
}

// ---------------------------------------------------------------------------
// 4) Fused softmax + threshold + compaction + sparse gather (one block/row).
// ---------------------------------------------------------------------------
__global__ void __launch_bounds__(288) k_smx_nbr() {
    __shared__ float ex[Nn];
    __shared__ float wred[9];
    __shared__ int wcnt[9], wbase[9];
    __shared__ int s_idx[CAP];
    __shared__ float s_val[CAP];
    __shared__ float s_diag;
    __shared__ int s_cnt;

    int b = blockIdx.y, n = blockIdx.x, tid = threadIdx.x;
    int wid = tid >> 5, lane = tid & 31;
    const float* row = g_S + (long long)b * NNL + (long long)n * Nn;

    float4 v0 = ((const float4*)row)[tid];
    float4 v1 = ((const float4*)row)[tid + 288];
    float mx = fmaxf(fmaxf(v0.x, v0.y), fmaxf(v0.z, v0.w));
    mx = fmaxf(mx, fmaxf(fmaxf(v1.x, v1.y), fmaxf(v1.z, v1.w)));
    #pragma unroll
    for (int o = 16; o; o >>= 1) mx = fmaxf(mx, __shfl_xor_sync(0xffffffffu, mx, o));
    if (!lane) wred[wid] = mx;
    __syncthreads();
    mx = wred[0];
    #pragma unroll
    for (int w = 1; w < 9; w++) mx = fmaxf(mx, wred[w]);
    __syncthreads();

    float4 e0, e1;
    e0.x = __expf(v0.x - mx); e0.y = __expf(v0.y - mx);
    e0.z = __expf(v0.z - mx); e0.w = __expf(v0.w - mx);
    e1.x = __expf(v1.x - mx); e1.y = __expf(v1.y - mx);
    e1.z = __expf(v1.z - mx); e1.w = __expf(v1.w - mx);
    ((float4*)ex)[tid] = e0;
    ((float4*)ex)[tid + 288] = e1;
    float s = e0.x + e0.y + e0.z + e0.w + e1.x + e1.y + e1.z + e1.w;
    #pragma unroll
    for (int o = 16; o; o >>= 1) s += __shfl_xor_sync(0xffffffffu, s, o);
    if (!lane) wred[wid] = s;
    __syncthreads();
    s = 0.f;
    #pragma unroll
    for (int w = 0; w < 9; w++) s += wred[w];
    float inv = 1.f / s;

    unsigned msks[8];
    int cnt = 0;
    int base_m = wid * 256;
    #pragma unroll
    for (int it = 0; it < 8; it++) {
        int m = base_m + it*32 + lane;
        float p = ex[m] * inv;
        bool ge = (p >= 0.01f);
        if (m == n) s_diag = ge ? p : 0.f;
        bool keep = ge && (m != n);
        unsigned k = __ballot_sync(0xffffffffu, keep);
        msks[it] = k;
        cnt += __popc(k);
    }
    if (!lane) wcnt[wid] = cnt;
    __syncthreads();
    if (tid == 0) {
        int t = 0;
        #pragma unroll
        for (int w = 0; w < 9; w++) { wbase[w] = t; t += wcnt[w]; }
        s_cnt = t;
    }
    __syncthreads();

    int bp = wbase[wid];
    #pragma unroll
    for (int it = 0; it < 8; it++) {
        unsigned k = msks[it];
        if ((k >> lane) & 1) {
            int m = base_m + it*32 + lane;
            int pos = bp + __popc(k & ((1u << lane) - 1));
            s_idx[pos] = m;
            s_val[pos] = ex[m] * inv;
        }
        bp += __popc(k);
    }
    __syncthreads();

    if (tid < Cc) {
        int c = tid;
        int y = n / Ww, x = n % Ww;
        const float* Xb = g_X + (size_t)b * NC;

        float acc = 0.f;
        if (y > 0)      acc += Xb[(size_t)(n - Ww) * Cc + c];
        if (y < Hh - 1) acc += Xb[(size_t)(n + Ww) * Cc + c];
        if (x > 0)      acc += Xb[(size_t)(n - 1) * Cc + c];
        if (x < Ww - 1) acc += Xb[(size_t)(n + 1) * Cc + c];

        int cnt2 = s_cnt;
        for (int i = 0; i < cnt2; i++)
            acc += s_val[i] * Xb[(size_t)s_idx[i] * Cc + c];

        size_t o = (size_t)b * NC + (size_t)n * Cc + c;
        __nv_bfloat16 nh = __float2bfloat16(acc);
        g_Nh[o] = nh;
        g_Nl[o] = __float2bfloat16(acc - __bfloat162float(nh));

        float xd = Xb[(size_t)n * Cc + c] * (1.f + s_diag);
        __nv_bfloat16 xh = __float2bfloat16(xd);
        g_Xdh[o] = xh;
        g_Xdl[o] = __float2bfloat16(xd - __bfloat162float(xh));
    }
}

// ---------------------------------------------------------------------------
// 5) Final: out = relu(w0@Xd^T + w1@nbr^T). CTA 128(d) x 64(n), 128 THREADS
//    (2x2 warps), warp tile 64d x 32n (acc 64 regs, LDSM/MMA = 1/4),
//    2-stage 48KB -> 2 CTAs/SM.
// ---------------------------------------------------------------------------
#define FW_TILE 8192
#define FX_TILE 4096
#define FIN_STAGE_B (4*FW_TILE + 4*FX_TILE)   // 49152
#define FIN_SMEM (2*FIN_STAGE_B)              // 98304

__global__ void __launch_bounds__(128, 2) k_final_mma(float* __restrict__ out) {
    extern __shared__ char smF[];
    int tid = threadIdx.x, wid = tid >> 5, lane = tid & 31;
    int b = blockIdx.z;
    int d0 = blockIdx.y * 128;
    int n0 = blockIdx.x * 64;

    const __nv_bfloat16* srcW[4] = {
        g_W0h + (size_t)d0*Cc, g_W0l + (size_t)d0*Cc,
        g_W1h + (size_t)d0*Cc, g_W1l + (size_t)d0*Cc
    };
    const __nv_bfloat16* srcX[4] = {
        g_Xdh + (size_t)b*NC + (size_t)n0*Cc, g_Xdl + (size_t)b*NC + (size_t)n0*Cc,
        g_Nh  + (size_t)b*NC + (size_t)n0*Cc, g_Nl  + (size_t)b*NC + (size_t)n0*Cc
    };

    int wd = (wid & 1) * 64;     // d offset (2 warps over 128)
    int wn = (wid >> 1) * 32;    // n offset (2 warps over 64)

    float acc[4][4][4];
    #pragma unroll
    for (int mi = 0; mi < 4; mi++)
        #pragma unroll
        for (int nj = 0; nj < 4; nj++)
            #pragma unroll
            for (int r = 0; r < 4; r++) acc[mi][nj][r] = 0.f;

    auto load_fin = [&](int st, int k0) {
        char* base = smF + st * FIN_STAGE_B;
        #pragma unroll
        for (int t = 0; t < 4; t++) {
            char* dst = base + t * FW_TILE;
            #pragma unroll
            for (int i = 0; i < 4; i++) {
                int chunk = i * 128 + tid;
                int r = chunk >> 2, c4 = chunk & 3;
                cp16(smem_u32(dst + swz(r*64 + c4*16)), srcW[t] + (size_t)r*Cc + k0 + c4*8);
            }
        }
        #pragma unroll
        for (int t = 0; t < 4; t++) {
            char* dst = base + 4*FW_TILE + t * FX_TILE;
            #pragma unroll
            for (int i = 0; i < 2; i++) {
                int chunk = i * 128 + tid;
                int r = chunk >> 2, c4 = chunk & 3;
                cp16(smem_u32(dst + swz(r*64 + c4*16)), srcX[t] + (size_t)r*Cc + k0 + c4*8);
            }
        }
    };

    load_fin(0, 0);
    CP_COMMIT();

    int arl = lane & 15, ach = lane >> 4;
    int b8r = (lane & 7) + ((lane >> 4) << 3);
    int bch = (lane >> 3) & 1;

    for (int ch = 0; ch < 8; ch++) {
        CP_WAIT(0);
        __syncthreads();
        if (ch < 7) {
            load_fin((ch + 1) & 1, (ch + 1) * 32);
            CP_COMMIT();
        }

        char* base = smF + (ch & 1) * FIN_STAGE_B;
        char* tW0h = base;
        char* tW0l = base + FW_TILE;
        char* tW1h = base + 2*FW_TILE;
        char* tW1l = base + 3*FW_TILE;
        char* tXh  = base + 4*FW_TILE;
        char* tXl  = base + 4*FW_TILE + FX_TILE;
        char* tNh  = base + 4*FW_TILE + 2*FX_TILE;
        char* tNl  = base + 4*FW_TILE + 3*FX_TILE;

        #pragma unroll
        for (int ks = 0; ks < 2; ks++) {
            uint32_t w0h[4][4], w0l[4][4], w1h[4][4], w1l[4][4];
            #pragma unroll
            for (int mi = 0; mi < 4; mi++) {
                LDSM4(w0h[mi], smem_u32(tW0h + swz((wd + mi*16 + arl)*64 + ks*32 + ach*16)));
                LDSM4(w0l[mi], smem_u32(tW0l + swz((wd + mi*16 + arl)*64 + ks*32 + ach*16)));
                LDSM4(w1h[mi], smem_u32(tW1h + swz((wd + mi*16 + arl)*64 + ks*32 + ach*16)));
                LDSM4(w1l[mi], smem_u32(tW1l + swz((wd + mi*16 + arl)*64 + ks*32 + ach*16)));
            }
            uint32_t bxh[8], bxl[8], bnh[8], bnl[8];
            #pragma unroll
            for (int t = 0; t < 2; t++) {
                LDSM4(bxh + t*4, smem_u32(tXh + swz((wn + t*16 + b8r)*64 + ks*32 + bch*16)));
                LDSM4(bxl + t*4, smem_u32(tXl + swz((wn + t*16 + b8r)*64 + ks*32 + bch*16)));
                LDSM4(bnh + t*4, smem_u32(tNh + swz((wn + t*16 + b8r)*64 + ks*32 + bch*16)));
                LDSM4(bnl + t*4, smem_u32(tNl + swz((wn + t*16 + b8r)*64 + ks*32 + bch*16)));
            }
            // term-major waves, per-acc term order preserved
            #pragma unroll
            for (int mi = 0; mi < 4; mi++)
                #pragma unroll
                for (int nj = 0; nj < 4; nj++) MMA16816(acc[mi][nj], w0h[mi], bxh + nj*2);
            #pragma unroll
            for (int mi = 0; mi < 4; mi++)
                #pragma unroll
                for (int nj = 0; nj < 4; nj++) MMA16816(acc[mi][nj], w0h[mi], bxl + nj*2);
            #pragma unroll
            for (int mi = 0; mi < 4; mi++)
                #pragma unroll
                for (int nj = 0; nj < 4; nj++) MMA16816(acc[mi][nj], w0l[mi], bxh + nj*2);
            #pragma unroll
            for (int mi = 0; mi < 4; mi++)
                #pragma unroll
                for (int nj = 0; nj < 4; nj++) MMA16816(acc[mi][nj], w1h[mi], bnh + nj*2);
            #pragma unroll
            for (int mi = 0; mi < 4; mi++)
                #pragma unroll
                for (int nj = 0; nj < 4; nj++) MMA16816(acc[mi][nj], w1h[mi], bnl + nj*2);
            #pragma unroll
            for (int mi = 0; mi < 4; mi++)
                #pragma unroll
                for (int nj = 0; nj < 4; nj++) MMA16816(acc[mi][nj], w1l[mi], bnh + nj*2);
        }
    }

    #pragma unroll
    for (int mi = 0; mi < 4; mi++)
        #pragma unroll
        for (int nj = 0; nj < 4; nj++) {
            int d = d0 + wd + mi*16 + (lane >> 2);
            int col = n0 + wn + nj*8 + (lane & 3)*2;
            float* p0 = out + ((size_t)b * Cc + d) * Nn + col;
            float2 v0;
            v0.x = fmaxf(acc[mi][nj][0], 0.f);
            v0.y = fmaxf(acc[mi][nj][1], 0.f);
            *(float2*)p0 = v0;
            float2 v1;
            v1.x = fmaxf(acc[mi][nj][2], 0.f);
            v1.y = fmaxf(acc[mi][nj][3], 0.f);
            *(float2*)(p0 + (size_t)8 * Nn) = v1;
        }
}

// ---------------------------------------------------------------------------
extern "C" void kernel_launch(void* const* d_in, const int* in_sizes, int n_in,
                              void* d_out, int out_size) {
    const float* x    = (const float*)d_in[0];
    const float* phi  = (const float*)d_in[1];
    const float* psi  = (const float*)d_in[2];
    const float* w0   = (const float*)d_in[3];
    const float* w1   = (const float*)d_in[4];
    float* out = (float*)d_out;

    cudaFuncSetAttribute(k_qk_mma,     cudaFuncAttributeMaxDynamicSharedMemorySize, QK_SMEM);
    cudaFuncSetAttribute(k_logits_mma, cudaFuncAttributeMaxDynamicSharedMemorySize, SM_LOGITS_BYTES);
    cudaFuncSetAttribute(k_final_mma,  cudaFuncAttributeMaxDynamicSharedMemorySize, FIN_SMEM);

    k_pack<<<dim3(Nn/32, Cc/32, Bb), dim3(32, 8)>>>(x);
    k_splitw<<<(Cc*Cc)/256, 256>>>(phi, psi, w0, w1);
    k_qk_mma<<<dim3(Cc/64, Nn/128, Bb), 128, QK_SMEM>>>();
    k_logits_mma<<<dim3(Nn/128, Nn/128, Bb), 128, SM_LOGITS_BYTES>>>();
    k_smx_nbr<<<dim3(Nn, Bb), 288>>>();
    k_final_mma<<<dim3(Nn/64, Cc/128, Bb), 128, FIN_SMEM>>>(out);
}

// round 15
// speedup vs baseline: 1.0530x; 1.0484x over previous
#include <cuda_runtime.h>
#include <cuda_bf16.h>
#include <cstdint>
#include <math.h>

#define Bb 8
#define Cc 256
#define Hh 48
#define Ww 48
#define Nn 2304
#define NC (Nn*Cc)
#define NR (Bb*Nn)
#define CAP 112
static const long long NNL = (long long)Nn * (long long)Nn;

// ---------------- scratch (static device globals — allocation-guard safe) ----
__device__ float g_S[(long long)Bb*Nn*Nn];       // logits fp32
__device__ __nv_bfloat16 g_Xhi[Bb*NC], g_Xlo[Bb*NC];
__device__ __nv_bfloat16 g_Qhi[Bb*NC], g_Qlo[Bb*NC];
__device__ __nv_bfloat16 g_Khi[Bb*NC], g_Klo[Bb*NC];
__device__ __nv_bfloat16 g_Xdh[Bb*NC], g_Xdl[Bb*NC];
__device__ __nv_bfloat16 g_Nh[Bb*NC],  g_Nl[Bb*NC];
__device__ __nv_bfloat16 g_PhiH[Cc*Cc], g_PhiL[Cc*Cc];
__device__ __nv_bfloat16 g_PsiH[Cc*Cc], g_PsiL[Cc*Cc];
__device__ __nv_bfloat16 g_W0h[Cc*Cc], g_W0l[Cc*Cc];
__device__ __nv_bfloat16 g_W1h[Cc*Cc], g_W1l[Cc*Cc];

// ---------------- PTX helpers (base-target features, sm_80 era) --------------
__device__ __forceinline__ uint32_t smem_u32(const void* p) {
    uint32_t a;
    asm("{ .reg .u64 t; cvta.to.shared.u64 t, %1; cvt.u32.u64 %0, t; }" : "=r"(a) : "l"(p));
    return a;
}
__device__ __forceinline__ void cp16(uint32_t dst, const void* src) {
    asm volatile("cp.async.cg.shared.global [%0], [%1], 16;" :: "r"(dst), "l"(src));
}
#define CP_COMMIT() asm volatile("cp.async.commit_group;" ::: "memory")
#define CP_WAIT(n)  asm volatile("cp.async.wait_group %0;" :: "n"(n) : "memory")

#define LDSM4(r, a) \
    asm volatile("ldmatrix.sync.aligned.m8n8.x4.shared.b16 {%0,%1,%2,%3}, [%4];" \
        : "=r"((r)[0]),"=r"((r)[1]),"=r"((r)[2]),"=r"((r)[3]) : "r"(a))
#define MMA16816(d, a, b) \
    asm volatile("mma.sync.aligned.m16n8k16.row.col.f32.bf16.bf16.f32 " \
        "{%0,%1,%2,%3}, {%4,%5,%6,%7}, {%8,%9}, {%0,%1,%2,%3};" \
        : "+f"((d)[0]),"+f"((d)[1]),"+f"((d)[2]),"+f"((d)[3]) \
        : "r"((a)[0]),"r"((a)[1]),"r"((a)[2]),"r"((a)[3]), "r"((b)[0]),"r"((b)[1]))

__device__ __forceinline__ uint32_t swz(uint32_t x) { return x ^ ((x >> 3) & 0x70); }

__device__ __forceinline__ void store_split2(__nv_bfloat16* hi, __nv_bfloat16* lo,
                                             size_t off, float a, float b) {
    __nv_bfloat16 ah = __float2bfloat16(a), bh = __float2bfloat16(b);
    __nv_bfloat162 h2; h2.x = ah; h2.y = bh;
    *(__nv_bfloat162*)(hi + off) = h2;
    __nv_bfloat162 l2;
    l2.x = __float2bfloat16(a - __bfloat162float(ah));
    l2.y = __float2bfloat16(b - __bfloat162float(bh));
    *(__nv_bfloat162*)(lo + off) = l2;
}

// ---------------------------------------------------------------------------
// 1) Fused pack + weight split.
//    z < Bb : pack x (B,C,N) -> bf16 hi/lo (B,N,C)  [no fp32 X copy]
//    z == Bb: split the 4 weight matrices (first 256 blocks of the slice)
// ---------------------------------------------------------------------------
__global__ void k_pack(const float* __restrict__ x,
                       const float* __restrict__ phi, const float* __restrict__ psi,
                       const float* __restrict__ w0,  const float* __restrict__ w1) {
    int z = blockIdx.z;
    int tx = threadIdx.x, ty = threadIdx.y;
    if (z == Bb) {
        int bid = blockIdx.y * 72 + blockIdx.x;
        if (bid >= 256) return;
        int i = bid * 256 + ty * 32 + tx;
        float v;
        __nv_bfloat16 h;
        v = phi[i]; h = __float2bfloat16(v); g_PhiH[i] = h; g_PhiL[i] = __float2bfloat16(v - __bfloat162float(h));
        v = psi[i]; h = __float2bfloat16(v); g_PsiH[i] = h; g_PsiL[i] = __float2bfloat16(v - __bfloat162float(h));
        v = w0[i];  h = __float2bfloat16(v); g_W0h[i]  = h; g_W0l[i]  = __float2bfloat16(v - __bfloat162float(h));
        v = w1[i];  h = __float2bfloat16(v); g_W1h[i]  = h; g_W1l[i]  = __float2bfloat16(v - __bfloat162float(h));
        return;
    }
    __shared__ float t[32][33];
    int b = z;
    int n0 = blockIdx.x * 32, c0 = blockIdx.y * 32;
    const float* xb = x + (size_t)b * Cc * Nn;
    #pragma unroll
    for (int i = 0; i < 4; i++)
        t[ty + 8*i][tx] = xb[(size_t)(c0 + ty + 8*i) * Nn + n0 + tx];
    __syncthreads();
    #pragma unroll
    for (int i = 0; i < 4; i++) {
        float v = t[tx][ty + 8*i];
        size_t o = (size_t)b * NC + (size_t)(n0 + ty + 8*i) * Cc + c0 + tx;
        __nv_bfloat16 h = __float2bfloat16(v);
        g_Xhi[o] = h;
        g_Xlo[o] = __float2bfloat16(v - __bfloat162float(h));
    }
}

// ---------------------------------------------------------------------------
// 2) Q/K dual projection. CTA 128(tok) x 64(d), 128 threads (2x2 warps),
//    warp 64tok x 32d dual-output, 3-stage pipeline, 2 CTAs/SM.
// ---------------------------------------------------------------------------
#define QKX_TILE 8192
#define QKW_TILE 4096
#define QK_STAGE_B (2*QKX_TILE + 4*QKW_TILE)  // 32768
#define QK_SMEM (3*QK_STAGE_B)                // 98304

__device__ __forceinline__ void qk_load_stage(char* smbase, int st,
        const __nv_bfloat16* Xh, const __nv_bfloat16* Xl,
        const __nv_bfloat16* PhH, const __nv_bfloat16* PhL,
        const __nv_bfloat16* PsH, const __nv_bfloat16* PsL,
        int k0, int tid) {
    char* base = smbase + st * QK_STAGE_B;
    const __nv_bfloat16* sa[2] = {Xh, Xl};
    #pragma unroll
    for (int t = 0; t < 2; t++) {
        char* dst = base + t * QKX_TILE;
        #pragma unroll
        for (int i = 0; i < 4; i++) {
            int chunk = i * 128 + tid;
            int r = chunk >> 2, c4 = chunk & 3;
            cp16(smem_u32(dst + swz(r*64 + c4*16)), sa[t] + (size_t)r*Cc + k0 + c4*8);
        }
    }
    const __nv_bfloat16* sb[4] = {PhH, PhL, PsH, PsL};
    #pragma unroll
    for (int t = 0; t < 4; t++) {
        char* dst = base + 2*QKX_TILE + t * QKW_TILE;
        #pragma unroll
        for (int i = 0; i < 2; i++) {
            int chunk = i * 128 + tid;
            int r = chunk >> 2, c4 = chunk & 3;
            cp16(smem_u32(dst + swz(r*64 + c4*16)), sb[t] + (size_t)r*Cc + k0 + c4*8);
        }
    }
}

__global__ void __launch_bounds__(128, 2) k_qk_mma() {
    extern __shared__ char smQ[];
    int tid = threadIdx.x, wid = tid >> 5, lane = tid & 31;
    int b = blockIdx.z;
    int arow = blockIdx.y * 128;
    int d0 = blockIdx.x * 64;

    const __nv_bfloat16* Xh = g_Xhi + (size_t)b*NC + (size_t)arow*Cc;
    const __nv_bfloat16* Xl = g_Xlo + (size_t)b*NC + (size_t)arow*Cc;
    const __nv_bfloat16* PhH = g_PhiH + (size_t)d0*Cc;
    const __nv_bfloat16* PhL = g_PhiL + (size_t)d0*Cc;
    const __nv_bfloat16* PsH = g_PsiH + (size_t)d0*Cc;
    const __nv_bfloat16* PsL = g_PsiL + (size_t)d0*Cc;

    int wm = (wid & 1) * 64;
    int wd = (wid >> 1) * 32;

    float accQ[4][4][4], accK[4][4][4];
    #pragma unroll
    for (int mi = 0; mi < 4; mi++)
        #pragma unroll
        for (int nj = 0; nj < 4; nj++)
            #pragma unroll
            for (int r = 0; r < 4; r++) { accQ[mi][nj][r] = 0.f; accK[mi][nj][r] = 0.f; }

    qk_load_stage(smQ, 0, Xh, Xl, PhH, PhL, PsH, PsL, 0, tid);
    CP_COMMIT();
    qk_load_stage(smQ, 1, Xh, Xl, PhH, PhL, PsH, PsL, 32, tid);
    CP_COMMIT();

    int arl = lane & 15, ach = lane >> 4;
    int b8r = (lane & 7) + ((lane >> 4) << 3);
    int bch = (lane >> 3) & 1;

    for (int ch = 0; ch < 8; ch++) {
        if (ch < 7) { CP_WAIT(1); } else { CP_WAIT(0); }
        __syncthreads();
        if (ch + 2 < 8) {
            qk_load_stage(smQ, (ch + 2) % 3, Xh, Xl, PhH, PhL, PsH, PsL, (ch + 2) * 32, tid);
            CP_COMMIT();
        }

        char* base = smQ + (ch % 3) * QK_STAGE_B;
        char* tXh  = base;
        char* tXl  = base + QKX_TILE;
        char* tPhH = base + 2*QKX_TILE;
        char* tPhL = base + 2*QKX_TILE + QKW_TILE;
        char* tPsH = base + 2*QKX_TILE + 2*QKW_TILE;
        char* tPsL = base + 2*QKX_TILE + 3*QKW_TILE;

        #pragma unroll
        for (int ks = 0; ks < 2; ks++) {
            uint32_t xh[4][4], xl[4][4];
            #pragma unroll
            for (int mi = 0; mi < 4; mi++) {
                LDSM4(xh[mi], smem_u32(tXh + swz((wm + mi*16 + arl)*64 + ks*32 + ach*16)));
                LDSM4(xl[mi], smem_u32(tXl + swz((wm + mi*16 + arl)*64 + ks*32 + ach*16)));
            }
            uint32_t bph[8], bpl[8], bsh[8], bsl[8];
            #pragma unroll
            for (int t = 0; t < 2; t++) {
                LDSM4(bph + t*4, smem_u32(tPhH + swz((wd + t*16 + b8r)*64 + ks*32 + bch*16)));
                LDSM4(bpl + t*4, smem_u32(tPhL + swz((wd + t*16 + b8r)*64 + ks*32 + bch*16)));
                LDSM4(bsh + t*4, smem_u32(tPsH + swz((wd + t*16 + b8r)*64 + ks*32 + bch*16)));
                LDSM4(bsl + t*4, smem_u32(tPsL + swz((wd + t*16 + b8r)*64 + ks*32 + bch*16)));
            }
            #pragma unroll
            for (int mi = 0; mi < 4; mi++)
                #pragma unroll
                for (int nj = 0; nj < 4; nj++) MMA16816(accQ[mi][nj], xh[mi], bph + nj*2);
            #pragma unroll
            for (int mi = 0; mi < 4; mi++)
                #pragma unroll
                for (int nj = 0; nj < 4; nj++) MMA16816(accK[mi][nj], xh[mi], bsh + nj*2);
            #pragma unroll
            for (int mi = 0; mi < 4; mi++)
                #pragma unroll
                for (int nj = 0; nj < 4; nj++) MMA16816(accQ[mi][nj], xh[mi], bpl + nj*2);
            #pragma unroll
            for (int mi = 0; mi < 4; mi++)
                #pragma unroll
                for (int nj = 0; nj < 4; nj++) MMA16816(accK[mi][nj], xh[mi], bsl + nj*2);
            #pragma unroll
            for (int mi = 0; mi < 4; mi++)
                #pragma unroll
                for (int nj = 0; nj < 4; nj++) MMA16816(accQ[mi][nj], xl[mi], bph + nj*2);
            #pragma unroll
            for (int mi = 0; mi < 4; mi++)
                #pragma unroll
                for (int nj = 0; nj < 4; nj++) MMA16816(accK[mi][nj], xl[mi], bsh + nj*2);
        }
    }

    #pragma unroll
    for (int mi = 0; mi < 4; mi++)
        #pragma unroll
        for (int nj = 0; nj < 4; nj++) {
            int r0 = arow + wm + mi*16 + (lane >> 2);
            int c0v = d0 + wd + nj*8 + (lane & 3)*2;
            size_t o0 = (size_t)b*NC + (size_t)r0*Cc + c0v;
            size_t o1 = o0 + (size_t)8*Cc;
            store_split2(g_Qhi, g_Qlo, o0, accQ[mi][nj][0], accQ[mi][nj][1]);
            store_split2(g_Qhi, g_Qlo, o1, accQ[mi][nj][2], accQ[mi][nj][3]);
            store_split2(g_Khi, g_Klo, o0, accK[mi][nj][0], accK[mi][nj][1]);
            store_split2(g_Khi, g_Klo, o1, accK[mi][nj][2], accK[mi][nj][3]);
        }
}

// ---------------------------------------------------------------------------
// 3) Logits: L = Q @ K^T. CTA 128x128, 128 threads, warp tile 64x64,
//    3-stage pipeline, 2 CTAs/SM. S stored with streaming hint.
// ---------------------------------------------------------------------------
#define LTILE_B 8192
#define LSTAGE_B (4*LTILE_B)
#define SM_LOGITS_BYTES (3*LSTAGE_B)

__device__ __forceinline__ void l_load_stage(char* smbase, int st,
        const __nv_bfloat16* Ah, const __nv_bfloat16* Al,
        const __nv_bfloat16* Bh, const __nv_bfloat16* Bl,
        int k0, int tid) {
    const __nv_bfloat16* srcs[4] = {Ah, Al, Bh, Bl};
    char* stb = smbase + st * LSTAGE_B;
    #pragma unroll
    for (int t = 0; t < 4; t++) {
        char* dst = stb + t * LTILE_B;
        #pragma unroll
        for (int i = 0; i < 4; i++) {
            int chunk = i * 128 + tid;
            int r = chunk >> 2, c4 = chunk & 3;
            cp16(smem_u32(dst + swz(r*64 + c4*16)), srcs[t] + (size_t)r*Cc + k0 + c4*8);
        }
    }
}

__global__ void __launch_bounds__(128, 2) k_logits_mma() {
    extern __shared__ char smL[];
    int tid = threadIdx.x, wid = tid >> 5, lane = tid & 31;
    int b = blockIdx.z;
    int arow = blockIdx.y * 128;
    int brow = blockIdx.x * 128;

    const __nv_bfloat16* Ah = g_Qhi + (size_t)b*NC + (size_t)arow*Cc;
    const __nv_bfloat16* Al = g_Qlo + (size_t)b*NC + (size_t)arow*Cc;
    const __nv_bfloat16* Bh = g_Khi + (size_t)b*NC + (size_t)brow*Cc;
    const __nv_bfloat16* Bl = g_Klo + (size_t)b*NC + (size_t)brow*Cc;

    int wm = (wid & 1) * 64;
    int wn = (wid >> 1) * 64;

    float acc[4][8][4];
    #pragma unroll
    for (int mi = 0; mi < 4; mi++)
        #pragma unroll
        for (int nj = 0; nj < 8; nj++)
            #pragma unroll
            for (int r = 0; r < 4; r++) acc[mi][nj][r] = 0.f;

    l_load_stage(smL, 0, Ah, Al, Bh, Bl, 0, tid);
    CP_COMMIT();
    l_load_stage(smL, 1, Ah, Al, Bh, Bl, 32, tid);
    CP_COMMIT();

    int arl = lane & 15, ach = lane >> 4;
    int b8r = (lane & 7) + ((lane >> 4) << 3);
    int bch = (lane >> 3) & 1;

    for (int ch = 0; ch < 8; ch++) {
        if (ch < 7) { CP_WAIT(1); } else { CP_WAIT(0); }
        __syncthreads();
        if (ch + 2 < 8) {
            l_load_stage(smL, (ch + 2) % 3, Ah, Al, Bh, Bl, (ch + 2) * 32, tid);
            CP_COMMIT();
        }

        char* stb = smL + (ch % 3) * LSTAGE_B;
        char* tAh = stb;
        char* tAl = stb + LTILE_B;
        char* tBh = stb + 2*LTILE_B;
        char* tBl = stb + 3*LTILE_B;

        #pragma unroll
        for (int ks = 0; ks < 2; ks++) {
            uint32_t ah[4][4], al[4][4], bh[16], bl[16];
            #pragma unroll
            for (int mi = 0; mi < 4; mi++) {
                LDSM4(ah[mi], smem_u32(tAh + swz((wm + mi*16 + arl)*64 + ks*32 + ach*16)));
                LDSM4(al[mi], smem_u32(tAl + swz((wm + mi*16 + arl)*64 + ks*32 + ach*16)));
            }
            #pragma unroll
            for (int t = 0; t < 4; t++) {
                LDSM4(bh + t*4, smem_u32(tBh + swz((wn + t*16 + b8r)*64 + ks*32 + bch*16)));
                LDSM4(bl + t*4, smem_u32(tBl + swz((wn + t*16 + b8r)*64 + ks*32 + bch*16)));
            }
            #pragma unroll
            for (int mi = 0; mi < 4; mi++)
                #pragma unroll
                for (int nj = 0; nj < 8; nj++) MMA16816(acc[mi][nj], ah[mi], bh + nj*2);
            #pragma unroll
            for (int mi = 0; mi < 4; mi++)
                #pragma unroll
                for (int nj = 0; nj < 8; nj++) MMA16816(acc[mi][nj], ah[mi], bl + nj*2);
            #pragma unroll
            for (int mi = 0; mi < 4; mi++)
                #pragma unroll
                for (int nj = 0; nj < 8; nj++) MMA16816(acc[mi][nj], al[mi], bh + nj*2);
        }
    }

    float* Cp = g_S + (size_t)b * NNL;
    int r0 = arow + wm + (lane >> 2);
    int c0 = brow + wn + (lane & 3) * 2;
    #pragma unroll
    for (int mi = 0; mi < 4; mi++)
        #pragma unroll
        for (int nj = 0; nj < 8; nj++) {
            float* p0 = Cp + (size_t)(r0 + mi*16) * Nn + c0 + nj*8;
            __stcs((float2*)p0, make_float2(acc[mi][nj][0], acc[mi][nj][1]));
            float* p1 = p0 + (size_t)8 * Nn;
            __stcs((float2*)p1, make_float2(acc[mi][nj][2], acc[mi][nj][3]));
        }
}

// ---------------------------------------------------------------------------
// 4) Fused softmax + threshold + compaction + sparse gather (one block/row).
//    S streamed with __ldcs; X reconstructed from bf16 hi+lo (L2-resident).
// ---------------------------------------------------------------------------
__global__ void __launch_bounds__(288) k_smx_nbr() {
    __shared__ float ex[Nn];
    __shared__ float wred[9];
    __shared__ int wcnt[9], wbase[9];
    __shared__ int s_idx[CAP];
    __shared__ float s_val[CAP];
    __shared__ float s_diag;
    __shared__ int s_cnt;

    int b = blockIdx.y, n = blockIdx.x, tid = threadIdx.x;
    int wid = tid >> 5, lane = tid & 31;
    const float* row = g_S + (long long)b * NNL + (long long)n * Nn;

    float4 v0 = __ldcs((const float4*)row + tid);
    float4 v1 = __ldcs((const float4*)row + tid + 288);
    float mx = fmaxf(fmaxf(v0.x, v0.y), fmaxf(v0.z, v0.w));
    mx = fmaxf(mx, fmaxf(fmaxf(v1.x, v1.y), fmaxf(v1.z, v1.w)));
    #pragma unroll
    for (int o = 16; o; o >>= 1) mx = fmaxf(mx, __shfl_xor_sync(0xffffffffu, mx, o));
    if (!lane) wred[wid] = mx;
    __syncthreads();
    mx = wred[0];
    #pragma unroll
    for (int w = 1; w < 9; w++) mx = fmaxf(mx, wred[w]);
    __syncthreads();

    float4 e0, e1;
    e0.x = __expf(v0.x - mx); e0.y = __expf(v0.y - mx);
    e0.z = __expf(v0.z - mx); e0.w = __expf(v0.w - mx);
    e1.x = __expf(v1.x - mx); e1.y = __expf(v1.y - mx);
    e1.z = __expf(v1.z - mx); e1.w = __expf(v1.w - mx);
    ((float4*)ex)[tid] = e0;
    ((float4*)ex)[tid + 288] = e1;
    float s = e0.x + e0.y + e0.z + e0.w + e1.x + e1.y + e1.z + e1.w;
    #pragma unroll
    for (int o = 16; o; o >>= 1) s += __shfl_xor_sync(0xffffffffu, s, o);
    if (!lane) wred[wid] = s;
    __syncthreads();
    s = 0.f;
    #pragma unroll
    for (int w = 0; w < 9; w++) s += wred[w];
    float inv = 1.f / s;

    unsigned msks[8];
    int cnt = 0;
    int base_m = wid * 256;
    #pragma unroll
    for (int it = 0; it < 8; it++) {
        int m = base_m + it*32 + lane;
        float p = ex[m] * inv;
        bool ge = (p >= 0.01f);
        if (m == n) s_diag = ge ? p : 0.f;
        bool keep = ge && (m != n);
        unsigned k = __ballot_sync(0xffffffffu, keep);
        msks[it] = k;
        cnt += __popc(k);
    }
    if (!lane) wcnt[wid] = cnt;
    __syncthreads();
    if (tid == 0) {
        int t = 0;
        #pragma unroll
        for (int w = 0; w < 9; w++) { wbase[w] = t; t += wcnt[w]; }
        s_cnt = t;
    }
    __syncthreads();

    int bp = wbase[wid];
    #pragma unroll
    for (int it = 0; it < 8; it++) {
        unsigned k = msks[it];
        if ((k >> lane) & 1) {
            int m = base_m + it*32 + lane;
            int pos = bp + __popc(k & ((1u << lane) - 1));
            s_idx[pos] = m;
            s_val[pos] = ex[m] * inv;
        }
        bp += __popc(k);
    }
    __syncthreads();

    if (tid < Cc) {
        int c = tid;
        int y = n / Ww, x = n % Ww;
        const __nv_bfloat16* Xh = g_Xhi + (size_t)b * NC;
        const __nv_bfloat16* Xl = g_Xlo + (size_t)b * NC;

        auto xval = [&](int rowi) -> float {
            return __bfloat162float(Xh[(size_t)rowi * Cc + c]) +
                   __bfloat162float(Xl[(size_t)rowi * Cc + c]);
        };

        float acc = 0.f;
        if (y > 0)      acc += xval(n - Ww);
        if (y < Hh - 1) acc += xval(n + Ww);
        if (x > 0)      acc += xval(n - 1);
        if (x < Ww - 1) acc += xval(n + 1);

        int cnt2 = s_cnt;
        int i = 0;
        for (; i + 2 <= cnt2; i += 2) {
            int i0 = s_idx[i], i1 = s_idx[i + 1];
            float p0 = s_val[i], p1 = s_val[i + 1];
            acc += p0 * xval(i0);
            acc += p1 * xval(i1);
        }
        if (i < cnt2)
            acc += s_val[i] * xval(s_idx[i]);

        size_t o = (size_t)b * NC + (size_t)n * Cc + c;
        __nv_bfloat16 nh = __float2bfloat16(acc);
        g_Nh[o] = nh;
        g_Nl[o] = __float2bfloat16(acc - __bfloat162float(nh));

        float xd = xval(n) * (1.f + s_diag);
        __nv_bfloat16 xh = __float2bfloat16(xd);
        g_Xdh[o] = xh;
        g_Xdl[o] = __float2bfloat16(xd - __bfloat162float(xh));
    }
}

// ---------------------------------------------------------------------------
// 5) Final: out = relu(w0@Xd^T + w1@nbr^T). CTA 128(d) x 64(n), 128 threads
//    (2x2 warps), warp 64d x 32n, 2-stage 48KB -> 2 CTAs/SM.
// ---------------------------------------------------------------------------
#define FW_TILE 8192
#define FX_TILE 4096
#define FIN_STAGE_B (4*FW_TILE + 4*FX_TILE)
#define FIN_SMEM (2*FIN_STAGE_B)

__global__ void __launch_bounds__(128, 2) k_final_mma(float* __restrict__ out) {
    extern __shared__ char smF[];
    int tid = threadIdx.x, wid = tid >> 5, lane = tid & 31;
    int b = blockIdx.z;
    int d0 = blockIdx.y * 128;
    int n0 = blockIdx.x * 64;

    const __nv_bfloat16* srcW[4] = {
        g_W0h + (size_t)d0*Cc, g_W0l + (size_t)d0*Cc,
        g_W1h + (size_t)d0*Cc, g_W1l + (size_t)d0*Cc
    };
    const __nv_bfloat16* srcX[4] = {
        g_Xdh + (size_t)b*NC + (size_t)n0*Cc, g_Xdl + (size_t)b*NC + (size_t)n0*Cc,
        g_Nh  + (size_t)b*NC + (size_t)n0*Cc, g_Nl  + (size_t)b*NC + (size_t)n0*Cc
    };

    int wd = (wid & 1) * 64;
    int wn = (wid >> 1) * 32;

    float acc[4][4][4];
    #pragma unroll
    for (int mi = 0; mi < 4; mi++)
        #pragma unroll
        for (int nj = 0; nj < 4; nj++)
            #pragma unroll
            for (int r = 0; r < 4; r++) acc[mi][nj][r] = 0.f;

    auto load_fin = [&](int st, int k0) {
        char* base = smF + st * FIN_STAGE_B;
        #pragma unroll
        for (int t = 0; t < 4; t++) {
            char* dst = base + t * FW_TILE;
            #pragma unroll
            for (int i = 0; i < 4; i++) {
                int chunk = i * 128 + tid;
                int r = chunk >> 2, c4 = chunk & 3;
                cp16(smem_u32(dst + swz(r*64 + c4*16)), srcW[t] + (size_t)r*Cc + k0 + c4*8);
            }
        }
        #pragma unroll
        for (int t = 0; t < 4; t++) {
            char* dst = base + 4*FW_TILE + t * FX_TILE;
            #pragma unroll
            for (int i = 0; i < 2; i++) {
                int chunk = i * 128 + tid;
                int r = chunk >> 2, c4 = chunk & 3;
                cp16(smem_u32(dst + swz(r*64 + c4*16)), srcX[t] + (size_t)r*Cc + k0 + c4*8);
            }
        }
    };

    load_fin(0, 0);
    CP_COMMIT();

    int arl = lane & 15, ach = lane >> 4;
    int b8r = (lane & 7) + ((lane >> 4) << 3);
    int bch = (lane >> 3) & 1;

    for (int ch = 0; ch < 8; ch++) {
        CP_WAIT(0);
        __syncthreads();
        if (ch < 7) {
            load_fin((ch + 1) & 1, (ch + 1) * 32);
            CP_COMMIT();
        }

        char* base = smF + (ch & 1) * FIN_STAGE_B;
        char* tW0h = base;
        char* tW0l = base + FW_TILE;
        char* tW1h = base + 2*FW_TILE;
        char* tW1l = base + 3*FW_TILE;
        char* tXh  = base + 4*FW_TILE;
        char* tXl  = base + 4*FW_TILE + FX_TILE;
        char* tNh  = base + 4*FW_TILE + 2*FX_TILE;
        char* tNl  = base + 4*FW_TILE + 3*FX_TILE;

        #pragma unroll
        for (int ks = 0; ks < 2; ks++) {
            uint32_t w0h[4][4], w0l[4][4], w1h[4][4], w1l[4][4];
            #pragma unroll
            for (int mi = 0; mi < 4; mi++) {
                LDSM4(w0h[mi], smem_u32(tW0h + swz((wd + mi*16 + arl)*64 + ks*32 + ach*16)));
                LDSM4(w0l[mi], smem_u32(tW0l + swz((wd + mi*16 + arl)*64 + ks*32 + ach*16)));
                LDSM4(w1h[mi], smem_u32(tW1h + swz((wd + mi*16 + arl)*64 + ks*32 + ach*16)));
                LDSM4(w1l[mi], smem_u32(tW1l + swz((wd + mi*16 + arl)*64 + ks*32 + ach*16)));
            }
            uint32_t bxh[8], bxl[8], bnh[8], bnl[8];
            #pragma unroll
            for (int t = 0; t < 2; t++) {
                LDSM4(bxh + t*4, smem_u32(tXh + swz((wn + t*16 + b8r)*64 + ks*32 + bch*16)));
                LDSM4(bxl + t*4, smem_u32(tXl + swz((wn + t*16 + b8r)*64 + ks*32 + bch*16)));
                LDSM4(bnh + t*4, smem_u32(tNh + swz((wn + t*16 + b8r)*64 + ks*32 + bch*16)));
                LDSM4(bnl + t*4, smem_u32(tNl + swz((wn + t*16 + b8r)*64 + ks*32 + bch*16)));
            }
            #pragma unroll
            for (int mi = 0; mi < 4; mi++)
                #pragma unroll
                for (int nj = 0; nj < 4; nj++) MMA16816(acc[mi][nj], w0h[mi], bxh + nj*2);
            #pragma unroll
            for (int mi = 0; mi < 4; mi++)
                #pragma unroll
                for (int nj = 0; nj < 4; nj++) MMA16816(acc[mi][nj], w0h[mi], bxl + nj*2);
            #pragma unroll
            for (int mi = 0; mi < 4; mi++)
                #pragma unroll
                for (int nj = 0; nj < 4; nj++) MMA16816(acc[mi][nj], w0l[mi], bxh + nj*2);
            #pragma unroll
            for (int mi = 0; mi < 4; mi++)
                #pragma unroll
                for (int nj = 0; nj < 4; nj++) MMA16816(acc[mi][nj], w1h[mi], bnh + nj*2);
            #pragma unroll
            for (int mi = 0; mi < 4; mi++)
                #pragma unroll
                for (int nj = 0; nj < 4; nj++) MMA16816(acc[mi][nj], w1h[mi], bnl + nj*2);
            #pragma unroll
            for (int mi = 0; mi < 4; mi++)
                #pragma unroll
                for (int nj = 0; nj < 4; nj++) MMA16816(acc[mi][nj], w1l[mi], bnh + nj*2);
        }
    }

    #pragma unroll
    for (int mi = 0; mi < 4; mi++)
        #pragma unroll
        for (int nj = 0; nj < 4; nj++) {
            int d = d0 + wd + mi*16 + (lane >> 2);
            int col = n0 + wn + nj*8 + (lane & 3)*2;
            float* p0 = out + ((size_t)b * Cc + d) * Nn + col;
            float2 v0;
            v0.x = fmaxf(acc[mi][nj][0], 0.f);
            v0.y = fmaxf(acc[mi][nj][1], 0.f);
            *(float2*)p0 = v0;
            float2 v1;
            v1.x = fmaxf(acc[mi][nj][2], 0.f);
            v1.y = fmaxf(acc[mi][nj][3], 0.f);
            *(float2*)(p0 + (size_t)8 * Nn) = v1;
        }
}

// ---------------------------------------------------------------------------
extern "C" void kernel_launch(void* const* d_in, const int* in_sizes, int n_in,
                              void* d_out, int out_size) {
    const float* x    = (const float*)d_in[0];
    const float* phi  = (const float*)d_in[1];
    const float* psi  = (const float*)d_in[2];
    const float* w0   = (const float*)d_in[3];
    const float* w1   = (const float*)d_in[4];
    float* out = (float*)d_out;

    cudaFuncSetAttribute(k_qk_mma,     cudaFuncAttributeMaxDynamicSharedMemorySize, QK_SMEM);
    cudaFuncSetAttribute(k_logits_mma, cudaFuncAttributeMaxDynamicSharedMemorySize, SM_LOGITS_BYTES);
    cudaFuncSetAttribute(k_final_mma,  cudaFuncAttributeMaxDynamicSharedMemorySize, FIN_SMEM);

    k_pack<<<dim3(Nn/32, Cc/32, Bb + 1), dim3(32, 8)>>>(x, phi, psi, w0, w1);
    k_qk_mma<<<dim3(Cc/64, Nn/128, Bb), 128, QK_SMEM>>>();
    k_logits_mma<<<dim3(Nn/128, Nn/128, Bb), 128, SM_LOGITS_BYTES>>>();
    k_smx_nbr<<<dim3(Nn, Bb), 288>>>();
    k_final_mma<<<dim3(Nn/64, Cc/128, Bb), 128, FIN_SMEM>>>(out);
}

// round 16
// speedup vs baseline: 1.0639x; 1.0103x over previous
#include <cuda_runtime.h>
#include <cuda_bf16.h>
#include <cstdint>
#include <math.h>

#define Bb 8
#define Cc 256
#define Hh 48
#define Ww 48
#define Nn 2304
#define NC (Nn*Cc)
#define NR (Bb*Nn)
#define CAP 112
static const long long NNL = (long long)Nn * (long long)Nn;

// ---------------- scratch (static device globals — allocation-guard safe) ----
__device__ float g_S[(long long)Bb*Nn*Nn];       // logits fp32
__device__ __nv_bfloat16 g_Xhi[Bb*NC], g_Xlo[Bb*NC];
__device__ __nv_bfloat162 g_Xp[Bb*NC];           // packed (hi,lo) for gather
__device__ __nv_bfloat16 g_Qhi[Bb*NC], g_Qlo[Bb*NC];
__device__ __nv_bfloat16 g_Khi[Bb*NC], g_Klo[Bb*NC];
__device__ __nv_bfloat16 g_Xdh[Bb*NC], g_Xdl[Bb*NC];
__device__ __nv_bfloat16 g_Nh[Bb*NC],  g_Nl[Bb*NC];
__device__ __nv_bfloat16 g_PhiH[Cc*Cc], g_PhiL[Cc*Cc];
__device__ __nv_bfloat16 g_PsiH[Cc*Cc], g_PsiL[Cc*Cc];
__device__ __nv_bfloat16 g_W0h[Cc*Cc], g_W0l[Cc*Cc];
__device__ __nv_bfloat16 g_W1h[Cc*Cc], g_W1l[Cc*Cc];

// ---------------- PTX helpers (base-target features, sm_80 era) --------------
__device__ __forceinline__ uint32_t smem_u32(const void* p) {
    uint32_t a;
    asm("{ .reg .u64 t; cvta.to.shared.u64 t, %1; cvt.u32.u64 %0, t; }" : "=r"(a) : "l"(p));
    return a;
}
__device__ __forceinline__ void cp16(uint32_t dst, const void* src) {
    asm volatile("cp.async.cg.shared.global [%0], [%1], 16;" :: "r"(dst), "l"(src));
}
#define CP_COMMIT() asm volatile("cp.async.commit_group;" ::: "memory")
#define CP_WAIT(n)  asm volatile("cp.async.wait_group %0;" :: "n"(n) : "memory")

#define LDSM4(r, a) \
    asm volatile("ldmatrix.sync.aligned.m8n8.x4.shared.b16 {%0,%1,%2,%3}, [%4];" \
        : "=r"((r)[0]),"=r"((r)[1]),"=r"((r)[2]),"=r"((r)[3]) : "r"(a))
#define MMA16816(d, a, b) \
    asm volatile("mma.sync.aligned.m16n8k16.row.col.f32.bf16.bf16.f32 " \
        "{%0,%1,%2,%3}, {%4,%5,%6,%7}, {%8,%9}, {%0,%1,%2,%3};" \
        : "+f"((d)[0]),"+f"((d)[1]),"+f"((d)[2]),"+f"((d)[3]) \
        : "r"((a)[0]),"r"((a)[1]),"r"((a)[2]),"r"((a)[3]), "r"((b)[0]),"r"((b)[1]))

__device__ __forceinline__ uint32_t swz(uint32_t x) { return x ^ ((x >> 3) & 0x70); }

__device__ __forceinline__ void store_split2(__nv_bfloat16* hi, __nv_bfloat16* lo,
                                             size_t off, float a, float b) {
    __nv_bfloat16 ah = __float2bfloat16(a), bh = __float2bfloat16(b);
    __nv_bfloat162 h2; h2.x = ah; h2.y = bh;
    *(__nv_bfloat162*)(hi + off) = h2;
    __nv_bfloat162 l2;
    l2.x = __float2bfloat16(a - __bfloat162float(ah));
    l2.y = __float2bfloat16(b - __bfloat162float(bh));
    *(__nv_bfloat162*)(lo + off) = l2;
}

// ---------------------------------------------------------------------------
// 1) Fused pack + weight split. Also emits packed (hi,lo) X for the gather.
// ---------------------------------------------------------------------------
__global__ void k_pack(const float* __restrict__ x,
                       const float* __restrict__ phi, const float* __restrict__ psi,
                       const float* __restrict__ w0,  const float* __restrict__ w1) {
    int z = blockIdx.z;
    int tx = threadIdx.x, ty = threadIdx.y;
    if (z == Bb) {
        int bid = blockIdx.y * 72 + blockIdx.x;
        if (bid >= 256) return;
        int i = bid * 256 + ty * 32 + tx;
        float v;
        __nv_bfloat16 h;
        v = phi[i]; h = __float2bfloat16(v); g_PhiH[i] = h; g_PhiL[i] = __float2bfloat16(v - __bfloat162float(h));
        v = psi[i]; h = __float2bfloat16(v); g_PsiH[i] = h; g_PsiL[i] = __float2bfloat16(v - __bfloat162float(h));
        v = w0[i];  h = __float2bfloat16(v); g_W0h[i]  = h; g_W0l[i]  = __float2bfloat16(v - __bfloat162float(h));
        v = w1[i];  h = __float2bfloat16(v); g_W1h[i]  = h; g_W1l[i]  = __float2bfloat16(v - __bfloat162float(h));
        return;
    }
    __shared__ float t[32][33];
    int b = z;
    int n0 = blockIdx.x * 32, c0 = blockIdx.y * 32;
    const float* xb = x + (size_t)b * Cc * Nn;
    #pragma unroll
    for (int i = 0; i < 4; i++)
        t[ty + 8*i][tx] = xb[(size_t)(c0 + ty + 8*i) * Nn + n0 + tx];
    __syncthreads();
    #pragma unroll
    for (int i = 0; i < 4; i++) {
        float v = t[tx][ty + 8*i];
        size_t o = (size_t)b * NC + (size_t)(n0 + ty + 8*i) * Cc + c0 + tx;
        __nv_bfloat16 h = __float2bfloat16(v);
        __nv_bfloat16 l = __float2bfloat16(v - __bfloat162float(h));
        g_Xhi[o] = h;
        g_Xlo[o] = l;
        __nv_bfloat162 p2; p2.x = h; p2.y = l;
        g_Xp[o] = p2;
    }
}

// ---------------------------------------------------------------------------
// 2) Q/K dual projection. CTA 128(tok) x 64(d), 128 threads (2x2 warps),
//    warp 64tok x 32d dual-output, 3-stage pipeline, 2 CTAs/SM.
// ---------------------------------------------------------------------------
#define QKX_TILE 8192
#define QKW_TILE 4096
#define QK_STAGE_B (2*QKX_TILE + 4*QKW_TILE)  // 32768
#define QK_SMEM (3*QK_STAGE_B)                // 98304

__device__ __forceinline__ void qk_load_stage(char* smbase, int st,
        const __nv_bfloat16* Xh, const __nv_bfloat16* Xl,
        const __nv_bfloat16* PhH, const __nv_bfloat16* PhL,
        const __nv_bfloat16* PsH, const __nv_bfloat16* PsL,
        int k0, int tid) {
    char* base = smbase + st * QK_STAGE_B;
    const __nv_bfloat16* sa[2] = {Xh, Xl};
    #pragma unroll
    for (int t = 0; t < 2; t++) {
        char* dst = base + t * QKX_TILE;
        #pragma unroll
        for (int i = 0; i < 4; i++) {
            int chunk = i * 128 + tid;
            int r = chunk >> 2, c4 = chunk & 3;
            cp16(smem_u32(dst + swz(r*64 + c4*16)), sa[t] + (size_t)r*Cc + k0 + c4*8);
        }
    }
    const __nv_bfloat16* sb[4] = {PhH, PhL, PsH, PsL};
    #pragma unroll
    for (int t = 0; t < 4; t++) {
        char* dst = base + 2*QKX_TILE + t * QKW_TILE;
        #pragma unroll
        for (int i = 0; i < 2; i++) {
            int chunk = i * 128 + tid;
            int r = chunk >> 2, c4 = chunk & 3;
            cp16(smem_u32(dst + swz(r*64 + c4*16)), sb[t] + (size_t)r*Cc + k0 + c4*8);
        }
    }
}

__global__ void __launch_bounds__(128, 2) k_qk_mma() {
    extern __shared__ char smQ[];
    int tid = threadIdx.x, wid = tid >> 5, lane = tid & 31;
    int b = blockIdx.z;
    int arow = blockIdx.y * 128;
    int d0 = blockIdx.x * 64;

    const __nv_bfloat16* Xh = g_Xhi + (size_t)b*NC + (size_t)arow*Cc;
    const __nv_bfloat16* Xl = g_Xlo + (size_t)b*NC + (size_t)arow*Cc;
    const __nv_bfloat16* PhH = g_PhiH + (size_t)d0*Cc;
    const __nv_bfloat16* PhL = g_PhiL + (size_t)d0*Cc;
    const __nv_bfloat16* PsH = g_PsiH + (size_t)d0*Cc;
    const __nv_bfloat16* PsL = g_PsiL + (size_t)d0*Cc;

    int wm = (wid & 1) * 64;
    int wd = (wid >> 1) * 32;

    float accQ[4][4][4], accK[4][4][4];
    #pragma unroll
    for (int mi = 0; mi < 4; mi++)
        #pragma unroll
        for (int nj = 0; nj < 4; nj++)
            #pragma unroll
            for (int r = 0; r < 4; r++) { accQ[mi][nj][r] = 0.f; accK[mi][nj][r] = 0.f; }

    qk_load_stage(smQ, 0, Xh, Xl, PhH, PhL, PsH, PsL, 0, tid);
    CP_COMMIT();
    qk_load_stage(smQ, 1, Xh, Xl, PhH, PhL, PsH, PsL, 32, tid);
    CP_COMMIT();

    int arl = lane & 15, ach = lane >> 4;
    int b8r = (lane & 7) + ((lane >> 4) << 3);
    int bch = (lane >> 3) & 1;

    for (int ch = 0; ch < 8; ch++) {
        if (ch < 7) { CP_WAIT(1); } else { CP_WAIT(0); }
        __syncthreads();
        if (ch + 2 < 8) {
            qk_load_stage(smQ, (ch + 2) % 3, Xh, Xl, PhH, PhL, PsH, PsL, (ch + 2) * 32, tid);
            CP_COMMIT();
        }

        char* base = smQ + (ch % 3) * QK_STAGE_B;
        char* tXh  = base;
        char* tXl  = base + QKX_TILE;
        char* tPhH = base + 2*QKX_TILE;
        char* tPhL = base + 2*QKX_TILE + QKW_TILE;
        char* tPsH = base + 2*QKX_TILE + 2*QKW_TILE;
        char* tPsL = base + 2*QKX_TILE + 3*QKW_TILE;

        #pragma unroll
        for (int ks = 0; ks < 2; ks++) {
            uint32_t xh[4][4], xl[4][4];
            #pragma unroll
            for (int mi = 0; mi < 4; mi++) {
                LDSM4(xh[mi], smem_u32(tXh + swz((wm + mi*16 + arl)*64 + ks*32 + ach*16)));
                LDSM4(xl[mi], smem_u32(tXl + swz((wm + mi*16 + arl)*64 + ks*32 + ach*16)));
            }
            uint32_t bph[8], bpl[8], bsh[8], bsl[8];
            #pragma unroll
            for (int t = 0; t < 2; t++) {
                LDSM4(bph + t*4, smem_u32(tPhH + swz((wd + t*16 + b8r)*64 + ks*32 + bch*16)));
                LDSM4(bpl + t*4, smem_u32(tPhL + swz((wd + t*16 + b8r)*64 + ks*32 + bch*16)));
                LDSM4(bsh + t*4, smem_u32(tPsH + swz((wd + t*16 + b8r)*64 + ks*32 + bch*16)));
                LDSM4(bsl + t*4, smem_u32(tPsL + swz((wd + t*16 + b8r)*64 + ks*32 + bch*16)));
            }
            #pragma unroll
            for (int mi = 0; mi < 4; mi++)
                #pragma unroll
                for (int nj = 0; nj < 4; nj++) MMA16816(accQ[mi][nj], xh[mi], bph + nj*2);
            #pragma unroll
            for (int mi = 0; mi < 4; mi++)
                #pragma unroll
                for (int nj = 0; nj < 4; nj++) MMA16816(accK[mi][nj], xh[mi], bsh + nj*2);
            #pragma unroll
            for (int mi = 0; mi < 4; mi++)
                #pragma unroll
                for (int nj = 0; nj < 4; nj++) MMA16816(accQ[mi][nj], xh[mi], bpl + nj*2);
            #pragma unroll
            for (int mi = 0; mi < 4; mi++)
                #pragma unroll
                for (int nj = 0; nj < 4; nj++) MMA16816(accK[mi][nj], xh[mi], bsl + nj*2);
            #pragma unroll
            for (int mi = 0; mi < 4; mi++)
                #pragma unroll
                for (int nj = 0; nj < 4; nj++) MMA16816(accQ[mi][nj], xl[mi], bph + nj*2);
            #pragma unroll
            for (int mi = 0; mi < 4; mi++)
                #pragma unroll
                for (int nj = 0; nj < 4; nj++) MMA16816(accK[mi][nj], xl[mi], bsh + nj*2);
        }
    }

    #pragma unroll
    for (int mi = 0; mi < 4; mi++)
        #pragma unroll
        for (int nj = 0; nj < 4; nj++) {
            int r0 = arow + wm + mi*16 + (lane >> 2);
            int c0v = d0 + wd + nj*8 + (lane & 3)*2;
            size_t o0 = (size_t)b*NC + (size_t)r0*Cc + c0v;
            size_t o1 = o0 + (size_t)8*Cc;
            store_split2(g_Qhi, g_Qlo, o0, accQ[mi][nj][0], accQ[mi][nj][1]);
            store_split2(g_Qhi, g_Qlo, o1, accQ[mi][nj][2], accQ[mi][nj][3]);
            store_split2(g_Khi, g_Klo, o0, accK[mi][nj][0], accK[mi][nj][1]);
            store_split2(g_Khi, g_Klo, o1, accK[mi][nj][2], accK[mi][nj][3]);
        }
}

// ---------------------------------------------------------------------------
// 3) Logits: L = Q @ K^T. CTA 128x128, 128 threads, warp tile 64x64,
//    3-stage pipeline, 2 CTAs/SM. S stored with streaming hint.
// ---------------------------------------------------------------------------
#define LTILE_B 8192
#define LSTAGE_B (4*LTILE_B)
#define SM_LOGITS_BYTES (3*LSTAGE_B)

__device__ __forceinline__ void l_load_stage(char* smbase, int st,
        const __nv_bfloat16* Ah, const __nv_bfloat16* Al,
        const __nv_bfloat16* Bh, const __nv_bfloat16* Bl,
        int k0, int tid) {
    const __nv_bfloat16* srcs[4] = {Ah, Al, Bh, Bl};
    char* stb = smbase + st * LSTAGE_B;
    #pragma unroll
    for (int t = 0; t < 4; t++) {
        char* dst = stb + t * LTILE_B;
        #pragma unroll
        for (int i = 0; i < 4; i++) {
            int chunk = i * 128 + tid;
            int r = chunk >> 2, c4 = chunk & 3;
            cp16(smem_u32(dst + swz(r*64 + c4*16)), srcs[t] + (size_t)r*Cc + k0 + c4*8);
        }
    }
}

__global__ void __launch_bounds__(128, 2) k_logits_mma() {
    extern __shared__ char smL[];
    int tid = threadIdx.x, wid = tid >> 5, lane = tid & 31;
    int b = blockIdx.z;
    int arow = blockIdx.y * 128;
    int brow = blockIdx.x * 128;

    const __nv_bfloat16* Ah = g_Qhi + (size_t)b*NC + (size_t)arow*Cc;
    const __nv_bfloat16* Al = g_Qlo + (size_t)b*NC + (size_t)arow*Cc;
    const __nv_bfloat16* Bh = g_Khi + (size_t)b*NC + (size_t)brow*Cc;
    const __nv_bfloat16* Bl = g_Klo + (size_t)b*NC + (size_t)brow*Cc;

    int wm = (wid & 1) * 64;
    int wn = (wid >> 1) * 64;

    float acc[4][8][4];
    #pragma unroll
    for (int mi = 0; mi < 4; mi++)
        #pragma unroll
        for (int nj = 0; nj < 8; nj++)
            #pragma unroll
            for (int r = 0; r < 4; r++) acc[mi][nj][r] = 0.f;

    l_load_stage(smL, 0, Ah, Al, Bh, Bl, 0, tid);
    CP_COMMIT();
    l_load_stage(smL, 1, Ah, Al, Bh, Bl, 32, tid);
    CP_COMMIT();

    int arl = lane & 15, ach = lane >> 4;
    int b8r = (lane & 7) + ((lane >> 4) << 3);
    int bch = (lane >> 3) & 1;

    for (int ch = 0; ch < 8; ch++) {
        if (ch < 7) { CP_WAIT(1); } else { CP_WAIT(0); }
        __syncthreads();
        if (ch + 2 < 8) {
            l_load_stage(smL, (ch + 2) % 3, Ah, Al, Bh, Bl, (ch + 2) * 32, tid);
            CP_COMMIT();
        }

        char* stb = smL + (ch % 3) * LSTAGE_B;
        char* tAh = stb;
        char* tAl = stb + LTILE_B;
        char* tBh = stb + 2*LTILE_B;
        char* tBl = stb + 3*LTILE_B;

        #pragma unroll
        for (int ks = 0; ks < 2; ks++) {
            uint32_t ah[4][4], al[4][4], bh[16], bl[16];
            #pragma unroll
            for (int mi = 0; mi < 4; mi++) {
                LDSM4(ah[mi], smem_u32(tAh + swz((wm + mi*16 + arl)*64 + ks*32 + ach*16)));
                LDSM4(al[mi], smem_u32(tAl + swz((wm + mi*16 + arl)*64 + ks*32 + ach*16)));
            }
            #pragma unroll
            for (int t = 0; t < 4; t++) {
                LDSM4(bh + t*4, smem_u32(tBh + swz((wn + t*16 + b8r)*64 + ks*32 + bch*16)));
                LDSM4(bl + t*4, smem_u32(tBl + swz((wn + t*16 + b8r)*64 + ks*32 + bch*16)));
            }
            #pragma unroll
            for (int mi = 0; mi < 4; mi++)
                #pragma unroll
                for (int nj = 0; nj < 8; nj++) MMA16816(acc[mi][nj], ah[mi], bh + nj*2);
            #pragma unroll
            for (int mi = 0; mi < 4; mi++)
                #pragma unroll
                for (int nj = 0; nj < 8; nj++) MMA16816(acc[mi][nj], ah[mi], bl + nj*2);
            #pragma unroll
            for (int mi = 0; mi < 4; mi++)
                #pragma unroll
                for (int nj = 0; nj < 8; nj++) MMA16816(acc[mi][nj], al[mi], bh + nj*2);
        }
    }

    float* Cp = g_S + (size_t)b * NNL;
    int r0 = arow + wm + (lane >> 2);
    int c0 = brow + wn + (lane & 3) * 2;
    #pragma unroll
    for (int mi = 0; mi < 4; mi++)
        #pragma unroll
        for (int nj = 0; nj < 8; nj++) {
            float* p0 = Cp + (size_t)(r0 + mi*16) * Nn + c0 + nj*8;
            __stcs((float2*)p0, make_float2(acc[mi][nj][0], acc[mi][nj][1]));
            float* p1 = p0 + (size_t)8 * Nn;
            __stcs((float2*)p1, make_float2(acc[mi][nj][2], acc[mi][nj][3]));
        }
}

// ---------------------------------------------------------------------------
// 4) Fused softmax + threshold + compaction + sparse gather.
//    Register-resident: warp wid owns span [wid*256,+256), thread lane owns
//    8 consecutive elements — no smem ex[] round trip. Packed X gather.
// ---------------------------------------------------------------------------
__global__ void __launch_bounds__(288) k_smx_nbr() {
    __shared__ float wred[9];
    __shared__ int wcnt[9], wbase[9];
    __shared__ int s_idx[CAP];
    __shared__ float s_val[CAP];
    __shared__ float s_diag;
    __shared__ int s_cnt;

    int b = blockIdx.y, n = blockIdx.x, tid = threadIdx.x;
    int wid = tid >> 5, lane = tid & 31;
    const float* row = g_S + (long long)b * NNL + (long long)n * Nn;

    int base_e = wid * 256 + lane * 8;       // this thread's 8 elements
    float4 v0 = __ldcs((const float4*)(row + base_e));
    float4 v1 = __ldcs((const float4*)(row + base_e + 4));
    float e[8];
    e[0] = v0.x; e[1] = v0.y; e[2] = v0.z; e[3] = v0.w;
    e[4] = v1.x; e[5] = v1.y; e[6] = v1.z; e[7] = v1.w;

    float mx = e[0];
    #pragma unroll
    for (int i = 1; i < 8; i++) mx = fmaxf(mx, e[i]);
    #pragma unroll
    for (int o = 16; o; o >>= 1) mx = fmaxf(mx, __shfl_xor_sync(0xffffffffu, mx, o));
    if (!lane) wred[wid] = mx;
    __syncthreads();
    mx = wred[0];
    #pragma unroll
    for (int w = 1; w < 9; w++) mx = fmaxf(mx, wred[w]);
    __syncthreads();

    float s = 0.f;
    #pragma unroll
    for (int i = 0; i < 8; i++) { e[i] = __expf(e[i] - mx); s += e[i]; }
    #pragma unroll
    for (int o = 16; o; o >>= 1) s += __shfl_xor_sync(0xffffffffu, s, o);
    if (!lane) wred[wid] = s;
    __syncthreads();
    s = 0.f;
    #pragma unroll
    for (int w = 0; w < 9; w++) s += wred[w];
    float inv = 1.f / s;

    // compaction on register values: round it tests element base_e + it
    float p[8];
    unsigned msks[8];
    int cnt = 0;
    #pragma unroll
    for (int it = 0; it < 8; it++) {
        int m = base_e + it;
        p[it] = e[it] * inv;
        bool ge = (p[it] >= 0.01f);
        if (m == n) s_diag = ge ? p[it] : 0.f;
        bool keep = ge && (m != n);
        unsigned k = __ballot_sync(0xffffffffu, keep);
        msks[it] = k;
        cnt += __popc(k);
    }
    if (!lane) wcnt[wid] = cnt;
    __syncthreads();
    if (tid == 0) {
        int t = 0;
        #pragma unroll
        for (int w = 0; w < 9; w++) { wbase[w] = t; t += wcnt[w]; }
        s_cnt = t;
    }
    __syncthreads();

    int bp = wbase[wid];
    #pragma unroll
    for (int it = 0; it < 8; it++) {
        unsigned k = msks[it];
        if ((k >> lane) & 1) {
            int pos = bp + __popc(k & ((1u << lane) - 1));
            s_idx[pos] = base_e + it;
            s_val[pos] = p[it];
        }
        bp += __popc(k);
    }
    __syncthreads();

    if (tid < Cc) {
        int c = tid;
        int y = n / Ww, x = n % Ww;
        const __nv_bfloat162* Xp = g_Xp + (size_t)b * NC;

        auto xval = [&](int rowi) -> float {
            __nv_bfloat162 p2 = Xp[(size_t)rowi * Cc + c];
            return __bfloat162float(p2.x) + __bfloat162float(p2.y);
        };

        float acc = 0.f;
        if (y > 0)      acc += xval(n - Ww);
        if (y < Hh - 1) acc += xval(n + Ww);
        if (x > 0)      acc += xval(n - 1);
        if (x < Ww - 1) acc += xval(n + 1);

        int cnt2 = s_cnt;
        int i = 0;
        for (; i + 2 <= cnt2; i += 2) {
            int i0 = s_idx[i], i1 = s_idx[i + 1];
            float p0 = s_val[i], p1 = s_val[i + 1];
            acc += p0 * xval(i0);
            acc += p1 * xval(i1);
        }
        if (i < cnt2)
            acc += s_val[i] * xval(s_idx[i]);

        size_t o = (size_t)b * NC + (size_t)n * Cc + c;
        __nv_bfloat16 nh = __float2bfloat16(acc);
        g_Nh[o] = nh;
        g_Nl[o] = __float2bfloat16(acc - __bfloat162float(nh));

        float xd = xval(n) * (1.f + s_diag);
        __nv_bfloat16 xh = __float2bfloat16(xd);
        g_Xdh[o] = xh;
        g_Xdl[o] = __float2bfloat16(xd - __bfloat162float(xh));
    }
}

// ---------------------------------------------------------------------------
// 5) Final: out = relu(w0@Xd^T + w1@nbr^T). CTA 128(d) x 64(n), 128 threads
//    (2x2 warps), warp 64d x 32n, 2-stage 48KB -> 2 CTAs/SM.
// ---------------------------------------------------------------------------
#define FW_TILE 8192
#define FX_TILE 4096
#define FIN_STAGE_B (4*FW_TILE + 4*FX_TILE)
#define FIN_SMEM (2*FIN_STAGE_B)

__global__ void __launch_bounds__(128, 2) k_final_mma(float* __restrict__ out) {
    extern __shared__ char smF[];
    int tid = threadIdx.x, wid = tid >> 5, lane = tid & 31;
    int b = blockIdx.z;
    int d0 = blockIdx.y * 128;
    int n0 = blockIdx.x * 64;

    const __nv_bfloat16* srcW[4] = {
        g_W0h + (size_t)d0*Cc, g_W0l + (size_t)d0*Cc,
        g_W1h + (size_t)d0*Cc, g_W1l + (size_t)d0*Cc
    };
    const __nv_bfloat16* srcX[4] = {
        g_Xdh + (size_t)b*NC + (size_t)n0*Cc, g_Xdl + (size_t)b*NC + (size_t)n0*Cc,
        g_Nh  + (size_t)b*NC + (size_t)n0*Cc, g_Nl  + (size_t)b*NC + (size_t)n0*Cc
    };

    int wd = (wid & 1) * 64;
    int wn = (wid >> 1) * 32;

    float acc[4][4][4];
    #pragma unroll
    for (int mi = 0; mi < 4; mi++)
        #pragma unroll
        for (int nj = 0; nj < 4; nj++)
            #pragma unroll
            for (int r = 0; r < 4; r++) acc[mi][nj][r] = 0.f;

    auto load_fin = [&](int st, int k0) {
        char* base = smF + st * FIN_STAGE_B;
        #pragma unroll
        for (int t = 0; t < 4; t++) {
            char* dst = base + t * FW_TILE;
            #pragma unroll
            for (int i = 0; i < 4; i++) {
                int chunk = i * 128 + tid;
                int r = chunk >> 2, c4 = chunk & 3;
                cp16(smem_u32(dst + swz(r*64 + c4*16)), srcW[t] + (size_t)r*Cc + k0 + c4*8);
            }
        }
        #pragma unroll
        for (int t = 0; t < 4; t++) {
            char* dst = base + 4*FW_TILE + t * FX_TILE;
            #pragma unroll
            for (int i = 0; i < 2; i++) {
                int chunk = i * 128 + tid;
                int r = chunk >> 2, c4 = chunk & 3;
                cp16(smem_u32(dst + swz(r*64 + c4*16)), srcX[t] + (size_t)r*Cc + k0 + c4*8);
            }
        }
    };

    load_fin(0, 0);
    CP_COMMIT();

    int arl = lane & 15, ach = lane >> 4;
    int b8r = (lane & 7) + ((lane >> 4) << 3);
    int bch = (lane >> 3) & 1;

    for (int ch = 0; ch < 8; ch++) {
        CP_WAIT(0);
        __syncthreads();
        if (ch < 7) {
            load_fin((ch + 1) & 1, (ch + 1) * 32);
            CP_COMMIT();
        }

        char* base = smF + (ch & 1) * FIN_STAGE_B;
        char* tW0h = base;
        char* tW0l = base + FW_TILE;
        char* tW1h = base + 2*FW_TILE;
        char* tW1l = base + 3*FW_TILE;
        char* tXh  = base + 4*FW_TILE;
        char* tXl  = base + 4*FW_TILE + FX_TILE;
        char* tNh  = base + 4*FW_TILE + 2*FX_TILE;
        char* tNl  = base + 4*FW_TILE + 3*FX_TILE;

        #pragma unroll
        for (int ks = 0; ks < 2; ks++) {
            uint32_t w0h[4][4], w0l[4][4], w1h[4][4], w1l[4][4];
            #pragma unroll
            for (int mi = 0; mi < 4; mi++) {
                LDSM4(w0h[mi], smem_u32(tW0h + swz((wd + mi*16 + arl)*64 + ks*32 + ach*16)));
                LDSM4(w0l[mi], smem_u32(tW0l + swz((wd + mi*16 + arl)*64 + ks*32 + ach*16)));
                LDSM4(w1h[mi], smem_u32(tW1h + swz((wd + mi*16 + arl)*64 + ks*32 + ach*16)));
                LDSM4(w1l[mi], smem_u32(tW1l + swz((wd + mi*16 + arl)*64 + ks*32 + ach*16)));
            }
            uint32_t bxh[8], bxl[8], bnh[8], bnl[8];
            #pragma unroll
            for (int t = 0; t < 2; t++) {
                LDSM4(bxh + t*4, smem_u32(tXh + swz((wn + t*16 + b8r)*64 + ks*32 + bch*16)));
                LDSM4(bxl + t*4, smem_u32(tXl + swz((wn + t*16 + b8r)*64 + ks*32 + bch*16)));
                LDSM4(bnh + t*4, smem_u32(tNh + swz((wn + t*16 + b8r)*64 + ks*32 + bch*16)));
                LDSM4(bnl + t*4, smem_u32(tNl + swz((wn + t*16 + b8r)*64 + ks*32 + bch*16)));
            }
            #pragma unroll
            for (int mi = 0; mi < 4; mi++)
                #pragma unroll
                for (int nj = 0; nj < 4; nj++) MMA16816(acc[mi][nj], w0h[mi], bxh + nj*2);
            #pragma unroll
            for (int mi = 0; mi < 4; mi++)
                #pragma unroll
                for (int nj = 0; nj < 4; nj++) MMA16816(acc[mi][nj], w0h[mi], bxl + nj*2);
            #pragma unroll
            for (int mi = 0; mi < 4; mi++)
                #pragma unroll
                for (int nj = 0; nj < 4; nj++) MMA16816(acc[mi][nj], w0l[mi], bxh + nj*2);
            #pragma unroll
            for (int mi = 0; mi < 4; mi++)
                #pragma unroll
                for (int nj = 0; nj < 4; nj++) MMA16816(acc[mi][nj], w1h[mi], bnh + nj*2);
            #pragma unroll
            for (int mi = 0; mi < 4; mi++)
                #pragma unroll
                for (int nj = 0; nj < 4; nj++) MMA16816(acc[mi][nj], w1h[mi], bnl + nj*2);
            #pragma unroll
            for (int mi = 0; mi < 4; mi++)
                #pragma unroll
                for (int nj = 0; nj < 4; nj++) MMA16816(acc[mi][nj], w1l[mi], bnh + nj*2);
        }
    }

    #pragma unroll
    for (int mi = 0; mi < 4; mi++)
        #pragma unroll
        for (int nj = 0; nj < 4; nj++) {
            int d = d0 + wd + mi*16 + (lane >> 2);
            int col = n0 + wn + nj*8 + (lane & 3)*2;
            float* p0 = out + ((size_t)b * Cc + d) * Nn + col;
            float2 v0;
            v0.x = fmaxf(acc[mi][nj][0], 0.f);
            v0.y = fmaxf(acc[mi][nj][1], 0.f);
            *(float2*)p0 = v0;
            float2 v1;
            v1.x = fmaxf(acc[mi][nj][2], 0.f);
            v1.y = fmaxf(acc[mi][nj][3], 0.f);
            *(float2*)(p0 + (size_t)8 * Nn) = v1;
        }
}

// ---------------------------------------------------------------------------
extern "C" void kernel_launch(void* const* d_in, const int* in_sizes, int n_in,
                              void* d_out, int out_size) {
    const float* x    = (const float*)d_in[0];
    const float* phi  = (const float*)d_in[1];
    const float* psi  = (const float*)d_in[2];
    const float* w0   = (const float*)d_in[3];
    const float* w1   = (const float*)d_in[4];
    float* out = (float*)d_out;

    cudaFuncSetAttribute(k_qk_mma,     cudaFuncAttributeMaxDynamicSharedMemorySize, QK_SMEM);
    cudaFuncSetAttribute(k_logits_mma, cudaFuncAttributeMaxDynamicSharedMemorySize, SM_LOGITS_BYTES);
    cudaFuncSetAttribute(k_final_mma,  cudaFuncAttributeMaxDynamicSharedMemorySize, FIN_SMEM);

    k_pack<<<dim3(Nn/32, Cc/32, Bb + 1), dim3(32, 8)>>>(x, phi, psi, w0, w1);
    k_qk_mma<<<dim3(Cc/64, Nn/128, Bb), 128, QK_SMEM>>>();
    k_logits_mma<<<dim3(Nn/128, Nn/128, Bb), 128, SM_LOGITS_BYTES>>>();
    k_smx_nbr<<<dim3(Nn, Bb), 288>>>();
    k_final_mma<<<dim3(Nn/64, Cc/128, Bb), 128, FIN_SMEM>>>(out);
}